// round 3
// baseline (speedup 1.0000x reference)
#include <cuda_runtime.h>
#include <cstdint>
#include <cstddef>

// Problem constants (fixed by the dataset).
#define N_NODES 300000
#define N_EDGES 4000000
#define IC      128
#define OC      64
#define NREL    7
#define NTYPE   4

// Device scratch (static allocation — no cudaMalloc allowed).
__device__ float g_h[(size_t)NREL * N_NODES * OC];   // per-relation transformed features
__device__ int   g_cnt[N_NODES * NREL];
__device__ float g_inv[N_NODES * NREL];

// ---------------------------------------------------------------------------
// Packed f32x2 FMA helpers (sm_103a FFMA2 — 2x scalar FFMA throughput).
// ---------------------------------------------------------------------------
__device__ __forceinline__ unsigned long long fma2(unsigned long long a,
                                                   unsigned long long b,
                                                   unsigned long long c) {
    unsigned long long d;
    asm("fma.rn.f32x2 %0, %1, %2, %3;" : "=l"(d) : "l"(a), "l"(b), "l"(c));
    return d;
}
__device__ __forceinline__ unsigned long long pack2(float lo, float hi) {
    unsigned long long d;
    asm("mov.b64 %0, {%1, %2};" : "=l"(d) : "f"(lo), "f"(hi));
    return d;
}
__device__ __forceinline__ float2 unpack2(unsigned long long v) {
    float lo, hi;
    asm("mov.b64 {%0, %1}, %2;" : "=f"(lo), "=f"(hi) : "l"(v));
    return make_float2(lo, hi);
}

// ---------------------------------------------------------------------------
// Phase 1: per-(dst, relation) edge counts -> 1/max(cnt,1)
// ---------------------------------------------------------------------------
__global__ void zero_cnt_kernel() {
    int i = blockIdx.x * blockDim.x + threadIdx.x;
    if (i < N_NODES * NREL) g_cnt[i] = 0;
}

__global__ void count_kernel(const int* __restrict__ edge_index,
                             const int* __restrict__ edge_type) {
    int e = blockIdx.x * blockDim.x + threadIdx.x;
    if (e < N_EDGES) {
        int dst = edge_index[N_EDGES + e];
        int rel = edge_type[e];
        atomicAdd(&g_cnt[dst * NREL + rel], 1);
    }
}

__global__ void inv_kernel() {
    int i = blockIdx.x * blockDim.x + threadIdx.x;
    if (i < N_NODES * NREL) {
        int c = g_cnt[i];
        g_inv[i] = 1.0f / (float)(c > 0 ? c : 1);
    }
}

// ---------------------------------------------------------------------------
// Phase 2: h[r][n][:] = x[n][:] @ W_rel[r]   (R x (N x 128 x 64) GEMM, fp32)
// Block: 128 threads, 32 nodes/tile, relation = blockIdx.y.
// smem: W (128x64 = 32KB) + x tile transposed (128x32 = 16KB) = 48KB static.
// ---------------------------------------------------------------------------
__global__ void __launch_bounds__(128) gemm_h_kernel(const float* __restrict__ x,
                                                     const float* __restrict__ W_rel) {
    __shared__ float sW[IC * OC];   // sW[k*64 + o]
    __shared__ float sX[IC * 32];   // sX[k*32 + node_local]  (transposed: bank-safe)

    const int r   = blockIdx.y;
    const int n0  = blockIdx.x * 32;      // N_NODES % 32 == 0
    const int tid = threadIdx.x;

    // Load W_rel[r] (8192 floats = 2048 float4)
    const float4* Wg = (const float4*)(W_rel + (size_t)r * IC * OC);
    float4* sW4 = (float4*)sW;
#pragma unroll
    for (int i = 0; i < 16; i++) sW4[tid + i * 128] = Wg[tid + i * 128];

    // Load x tile transposed (32 rows x 128 cols = 1024 float4)
    const float4* Xg = (const float4*)(x + (size_t)n0 * IC);
#pragma unroll
    for (int j = 0; j < 8; j++) {
        int idx = tid + j * 128;      // 0..1023
        int row = idx >> 5;           // 32 float4 per row
        int c4  = idx & 31;
        float4 v = Xg[idx];
        int k = c4 * 4;
        sX[(k + 0) * 32 + row] = v.x;
        sX[(k + 1) * 32 + row] = v.y;
        sX[(k + 2) * 32 + row] = v.z;
        sX[(k + 3) * 32 + row] = v.w;
    }
    __syncthreads();

    const int nl = tid >> 2;          // node within tile
    const int ob = (tid & 3) * 16;    // output base

    unsigned long long acc[8];
#pragma unroll
    for (int j = 0; j < 8; j++) acc[j] = 0ULL;

#pragma unroll 4
    for (int k = 0; k < IC; k++) {
        float xv = sX[k * 32 + nl];
        unsigned long long xx = pack2(xv, xv);
        const ulonglong2* wr = (const ulonglong2*)(sW + k * OC + ob);
#pragma unroll
        for (int j = 0; j < 4; j++) {
            ulonglong2 w = wr[j];
            acc[2 * j]     = fma2(w.x, xx, acc[2 * j]);
            acc[2 * j + 1] = fma2(w.y, xx, acc[2 * j + 1]);
        }
    }

    float2* hp = (float2*)(g_h + ((size_t)r * N_NODES + (n0 + nl)) * OC + ob);
#pragma unroll
    for (int j = 0; j < 8; j++) hp[j] = unpack2(acc[j]);
}

// ---------------------------------------------------------------------------
// Phase 3: out[n][:] = x[n][:] @ W_root[node_type[n]] + b_root[node_type[n]]
// Grid (N/32, NTYPE): block (.,t) caches W_root[t] (32KB) + x tile (16KB),
// and only the threads whose node has type t compute/store. Every node is
// written exactly once, which initializes the poisoned d_out before scatter.
// All static smem (48KB) — no cudaFuncSetAttribute needed.
// ---------------------------------------------------------------------------
__global__ void __launch_bounds__(128) root_kernel(const float* __restrict__ x,
                                                   const int* __restrict__ node_type,
                                                   const float* __restrict__ W_root,
                                                   const float* __restrict__ b_root,
                                                   float* __restrict__ out) {
    __shared__ float sW[IC * OC];
    __shared__ float sX[IC * 32];

    const int t   = blockIdx.y;
    const int n0  = blockIdx.x * 32;
    const int tid = threadIdx.x;

    const float4* Wg = (const float4*)(W_root + (size_t)t * IC * OC);
    float4* sW4 = (float4*)sW;
#pragma unroll
    for (int i = 0; i < 16; i++) sW4[tid + i * 128] = Wg[tid + i * 128];

    const float4* Xg = (const float4*)(x + (size_t)n0 * IC);
#pragma unroll
    for (int j = 0; j < 8; j++) {
        int idx = tid + j * 128;
        int row = idx >> 5;
        int c4  = idx & 31;
        float4 v = Xg[idx];
        int k = c4 * 4;
        sX[(k + 0) * 32 + row] = v.x;
        sX[(k + 1) * 32 + row] = v.y;
        sX[(k + 2) * 32 + row] = v.z;
        sX[(k + 3) * 32 + row] = v.w;
    }
    __syncthreads();

    const int nl = tid >> 2;
    const int ob = (tid & 3) * 16;
    const int n  = n0 + nl;
    if (node_type[n] != t) return;    // another block (same n0, right t) owns this node

    unsigned long long acc[8];
#pragma unroll
    for (int j = 0; j < 8; j++) acc[j] = 0ULL;

#pragma unroll 4
    for (int k = 0; k < IC; k++) {
        float xv = sX[k * 32 + nl];
        unsigned long long xx = pack2(xv, xv);
        const ulonglong2* wr = (const ulonglong2*)(sW + k * OC + ob);
#pragma unroll
        for (int j = 0; j < 4; j++) {
            ulonglong2 w = wr[j];
            acc[2 * j]     = fma2(w.x, xx, acc[2 * j]);
            acc[2 * j + 1] = fma2(w.y, xx, acc[2 * j + 1]);
        }
    }

    const float* bp = b_root + t * OC + ob;
    float* op = out + (size_t)n * OC + ob;
#pragma unroll
    for (int j = 0; j < 8; j++) {
        float2 v = unpack2(acc[j]);
        op[2 * j]     = v.x + bp[2 * j];
        op[2 * j + 1] = v.y + bp[2 * j + 1];
    }
}

// ---------------------------------------------------------------------------
// Phase 4: scatter  out[dst] += h[rel][src] * inv[dst*R+rel]
// 16 threads per edge, each commits one float4 via the sm_90+ vector atomic.
// ---------------------------------------------------------------------------
__global__ void __launch_bounds__(256) scatter_kernel(const int* __restrict__ edge_index,
                                                      const int* __restrict__ edge_type,
                                                      float* __restrict__ out) {
    const int tid  = threadIdx.x;
    const int e    = blockIdx.x * 16 + (tid >> 4);   // N_EDGES % 16 == 0
    const int lane = tid & 15;

    const int src = edge_index[e];
    const int dst = edge_index[N_EDGES + e];
    const int rel = edge_type[e];
    const float w = g_inv[dst * NREL + rel];

    const float4* hp = (const float4*)(g_h + ((size_t)rel * N_NODES + src) * OC);
    float4 v = hp[lane];
    v.x *= w; v.y *= w; v.z *= w; v.w *= w;

    float4* op = (float4*)(out + (size_t)dst * OC + lane * 4);
#if __CUDA_ARCH__ >= 900
    atomicAdd(op, v);                 // RED.ADD.V4.F32
#else
    float* os = (float*)op;
    atomicAdd(os + 0, v.x);
    atomicAdd(os + 1, v.y);
    atomicAdd(os + 2, v.z);
    atomicAdd(os + 3, v.w);
#endif
}

// ---------------------------------------------------------------------------
// Launch
// ---------------------------------------------------------------------------
extern "C" void kernel_launch(void* const* d_in, const int* in_sizes, int n_in,
                              void* d_out, int out_size) {
    const float* x          = (const float*)d_in[0];
    const int*   edge_index = (const int*)d_in[1];
    const int*   edge_type  = (const int*)d_in[2];
    const int*   node_type  = (const int*)d_in[3];
    const float* W_rel      = (const float*)d_in[4];
    const float* W_root     = (const float*)d_in[5];
    const float* b_root     = (const float*)d_in[6];
    float*       out        = (float*)d_out;

    const int nr = N_NODES * NREL;
    zero_cnt_kernel<<<(nr + 255) / 256, 256>>>();
    count_kernel<<<(N_EDGES + 255) / 256, 256>>>(edge_index, edge_type);
    inv_kernel<<<(nr + 255) / 256, 256>>>();

    gemm_h_kernel<<<dim3(N_NODES / 32, NREL), 128>>>(x, W_rel);

    root_kernel<<<dim3(N_NODES / 32, NTYPE), 128>>>(x, node_type, W_root, b_root, out);

    scatter_kernel<<<N_EDGES / 16, 256>>>(edge_index, edge_type, out);
}

// round 5
// speedup vs baseline: 2.6529x; 2.6529x over previous
#include <cuda_runtime.h>
#include <cstdint>
#include <cstddef>

// Problem constants (fixed by the dataset).
#define N_NODES 300000
#define N_EDGES 4000000
#define IC      128
#define OC      64
#define NREL    7
#define NTYPE   4
#define TILE_N  64
#define NBLK    ((N_NODES + TILE_N - 1) / TILE_N)

// Device scratch (static allocation — no cudaMalloc allowed).
__device__ float g_h[(size_t)NREL * N_NODES * OC];   // per-relation transformed features
__device__ int   g_cnt[N_NODES * NREL];
__device__ float g_inv[N_NODES * NREL];

// ---------------------------------------------------------------------------
// Packed f32x2 FMA helpers (sm_103a FFMA2 — 2x scalar FFMA throughput).
// ---------------------------------------------------------------------------
__device__ __forceinline__ unsigned long long fma2(unsigned long long a,
                                                   unsigned long long b,
                                                   unsigned long long c) {
    unsigned long long d;
    asm("fma.rn.f32x2 %0, %1, %2, %3;" : "=l"(d) : "l"(a), "l"(b), "l"(c));
    return d;
}
__device__ __forceinline__ unsigned long long pack2(float lo, float hi) {
    unsigned long long d;
    asm("mov.b64 %0, {%1, %2};" : "=l"(d) : "f"(lo), "f"(hi));
    return d;
}
__device__ __forceinline__ float2 unpack2(unsigned long long v) {
    float lo, hi;
    asm("mov.b64 {%0, %1}, %2;" : "=f"(lo), "=f"(hi) : "l"(v));
    return make_float2(lo, hi);
}

// ---------------------------------------------------------------------------
// Phase 1: per-(dst, relation) edge counts -> 1/max(cnt,1)
// ---------------------------------------------------------------------------
__global__ void zero_cnt_kernel() {
    int i = blockIdx.x * blockDim.x + threadIdx.x;
    if (i < N_NODES * NREL) g_cnt[i] = 0;
}

__global__ void count_kernel(const int* __restrict__ edge_index,
                             const int* __restrict__ edge_type) {
    int e = blockIdx.x * blockDim.x + threadIdx.x;
    if (e < N_EDGES) {
        int dst = edge_index[N_EDGES + e];
        int rel = edge_type[e];
        atomicAdd(&g_cnt[dst * NREL + rel], 1);
    }
}

__global__ void inv_kernel() {
    int i = blockIdx.x * blockDim.x + threadIdx.x;
    if (i < N_NODES * NREL) {
        int c = g_cnt[i];
        g_inv[i] = 1.0f / (float)(c > 0 ? c : 1);
    }
}

// ---------------------------------------------------------------------------
// Phase 2+3 fused: 11 weight passes over a 64-node x-tile.
//   pass 0..6  : h[r][n][:] = x[n][:] @ W_rel[r]          -> g_h
//   pass 7..10 : out[n][:]  = x[n][:] @ W_root[t] + b[t]  (store iff type==t)
// 128 threads; thread (tx=tid&7, ty=tid>>3) computes 8 nodes x 4 outputs as
// 16 f32x2 accumulators (nodes paired). Per k: 4 LDS.128 + 16 FFMA2.
// smem: sWd = W duplicated as f32x2 (64KB), sX = x transposed (32KB).
// ---------------------------------------------------------------------------
__global__ void __launch_bounds__(128) fused_gemm_kernel(
        const float* __restrict__ x,
        const int*   __restrict__ node_type,
        const float* __restrict__ W_rel,
        const float* __restrict__ W_root,
        const float* __restrict__ b_root,
        float* __restrict__ out) {
    extern __shared__ char smem_raw[];
    unsigned long long* sWd = (unsigned long long*)smem_raw;            // [IC*OC]
    float* sX = (float*)(smem_raw + (size_t)IC * OC * 8);               // [IC*TILE_N]

    const int tid = threadIdx.x;
    const int n0  = blockIdx.x * TILE_N;
    const int tx  = tid & 7;      // node group: nodes tx*8 .. tx*8+7
    const int ty  = tid >> 3;     // output group: outs ty*4 .. ty*4+3

    // ---- stage x transposed (conflict-free scalar writes: bank = node%32) ----
    {
        const int snode = tid & 63;
        const int shalf = tid >> 6;
        const bool valid = (n0 + snode) < N_NODES;
        const float4* xrow = (const float4*)(x + (size_t)(n0 + snode) * IC) + shalf * 16;
#pragma unroll
        for (int j = 0; j < 16; j++) {
            float4 v = valid ? xrow[j] : make_float4(0.f, 0.f, 0.f, 0.f);
            int c = (shalf * 16 + j) * 4;
            sX[(c + 0) * TILE_N + snode] = v.x;
            sX[(c + 1) * TILE_N + snode] = v.y;
            sX[(c + 2) * TILE_N + snode] = v.z;
            sX[(c + 3) * TILE_N + snode] = v.w;
        }
    }

    // preload node types for the root passes' masked stores
    int ntv[8];
#pragma unroll
    for (int i = 0; i < 8; i++) {
        int n = n0 + tx * 8 + i;
        ntv[i] = (n < N_NODES) ? node_type[n] : -1;
    }

    for (int pass = 0; pass < NREL + NTYPE; pass++) {
        const float* Wg = (pass < NREL)
            ? (W_rel  + (size_t)pass * IC * OC)
            : (W_root + (size_t)(pass - NREL) * IC * OC);

        __syncthreads();   // previous pass finished reading sWd (also covers sX stage)
        // Stage ALL IC*OC = 8192 weights (64 per thread), duplicated into f32x2.
#pragma unroll
        for (int j = 0; j < 64; j++) {
            int idx = j * 128 + tid;      // linear over [k][o] — coalesced read
            float v = Wg[idx];
            sWd[idx] = pack2(v, v);       // STS.64, 2-way conflict
        }
        __syncthreads();

        unsigned long long acc[4][4];
#pragma unroll
        for (int a = 0; a < 4; a++)
#pragma unroll
            for (int b = 0; b < 4; b++) acc[a][b] = 0ULL;

        const ulonglong2* xp = (const ulonglong2*)(sX + tx * 8);
        const ulonglong2* wp = (const ulonglong2*)(sWd + ty * 4);
#pragma unroll 4
        for (int k = 0; k < IC; k++) {
            ulonglong2 xa = xp[0], xb = xp[1];     // 4 node-pairs (f32x2 each)
            ulonglong2 w0 = wp[0], w1 = wp[1];     // 4 duplicated weights
            unsigned long long xq[4] = {xa.x, xa.y, xb.x, xb.y};
            unsigned long long wq[4] = {w0.x, w0.y, w1.x, w1.y};
#pragma unroll
            for (int a = 0; a < 4; a++)
#pragma unroll
                for (int b = 0; b < 4; b++)
                    acc[a][b] = fma2(xq[a], wq[b], acc[a][b]);
            xp += TILE_N / 4;   // next k row of sX (64 floats)
            wp += OC / 2;       // next k row of sWd (64 ull)
        }

        if (pass < NREL) {
            float* hb = g_h + (size_t)pass * N_NODES * OC;
#pragma unroll
            for (int a = 0; a < 4; a++) {
                float2 u0 = unpack2(acc[a][0]);
                float2 u1 = unpack2(acc[a][1]);
                float2 u2 = unpack2(acc[a][2]);
                float2 u3 = unpack2(acc[a][3]);
                int nA = n0 + tx * 8 + a * 2;
                if (nA < N_NODES)
                    *(float4*)(hb + (size_t)nA * OC + ty * 4) =
                        make_float4(u0.x, u1.x, u2.x, u3.x);
                if (nA + 1 < N_NODES)
                    *(float4*)(hb + (size_t)(nA + 1) * OC + ty * 4) =
                        make_float4(u0.y, u1.y, u2.y, u3.y);
            }
        } else {
            int t = pass - NREL;
            float4 bb = *(const float4*)(b_root + t * OC + ty * 4);
#pragma unroll
            for (int a = 0; a < 4; a++) {
                float2 u0 = unpack2(acc[a][0]);
                float2 u1 = unpack2(acc[a][1]);
                float2 u2 = unpack2(acc[a][2]);
                float2 u3 = unpack2(acc[a][3]);
                int nA = n0 + tx * 8 + a * 2;
                if (ntv[a * 2] == t)
                    *(float4*)(out + (size_t)nA * OC + ty * 4) =
                        make_float4(u0.x + bb.x, u1.x + bb.y, u2.x + bb.z, u3.x + bb.w);
                if (ntv[a * 2 + 1] == t)
                    *(float4*)(out + (size_t)(nA + 1) * OC + ty * 4) =
                        make_float4(u0.y + bb.x, u1.y + bb.y, u2.y + bb.z, u3.y + bb.w);
            }
        }
    }
}

// ---------------------------------------------------------------------------
// Phase 4: scatter  out[dst] += h[rel][src] * inv[dst*R+rel]
// 16 threads per edge, each commits one float4 via the sm_90+ vector atomic.
// ---------------------------------------------------------------------------
__global__ void __launch_bounds__(256) scatter_kernel(const int* __restrict__ edge_index,
                                                      const int* __restrict__ edge_type,
                                                      float* __restrict__ out) {
    const int tid  = threadIdx.x;
    const int e    = blockIdx.x * 16 + (tid >> 4);   // N_EDGES % 16 == 0
    const int lane = tid & 15;

    const int src = edge_index[e];
    const int dst = edge_index[N_EDGES + e];
    const int rel = edge_type[e];
    const float w = g_inv[dst * NREL + rel];

    const float4* hp = (const float4*)(g_h + ((size_t)rel * N_NODES + src) * OC);
    float4 v = hp[lane];
    v.x *= w; v.y *= w; v.z *= w; v.w *= w;

    float4* op = (float4*)(out + (size_t)dst * OC + lane * 4);
#if __CUDA_ARCH__ >= 900
    atomicAdd(op, v);                 // RED.ADD.V4.F32
#else
    float* os = (float*)op;
    atomicAdd(os + 0, v.x);
    atomicAdd(os + 1, v.y);
    atomicAdd(os + 2, v.z);
    atomicAdd(os + 3, v.w);
#endif
}

// ---------------------------------------------------------------------------
// Launch
// ---------------------------------------------------------------------------
extern "C" void kernel_launch(void* const* d_in, const int* in_sizes, int n_in,
                              void* d_out, int out_size) {
    const float* x          = (const float*)d_in[0];
    const int*   edge_index = (const int*)d_in[1];
    const int*   edge_type  = (const int*)d_in[2];
    const int*   node_type  = (const int*)d_in[3];
    const float* W_rel      = (const float*)d_in[4];
    const float* W_root     = (const float*)d_in[5];
    const float* b_root     = (const float*)d_in[6];
    float*       out        = (float*)d_out;

    const int nr = N_NODES * NREL;
    zero_cnt_kernel<<<(nr + 255) / 256, 256>>>();
    count_kernel<<<(N_EDGES + 255) / 256, 256>>>(edge_index, edge_type);
    inv_kernel<<<(nr + 255) / 256, 256>>>();

    const size_t fused_smem = (size_t)IC * OC * 8 + (size_t)IC * TILE_N * 4; // 96KB
    (void)cudaFuncSetAttribute(fused_gemm_kernel,
                               cudaFuncAttributeMaxDynamicSharedMemorySize,
                               (int)fused_smem);
    fused_gemm_kernel<<<NBLK, 128, fused_smem>>>(x, node_type, W_rel, W_root,
                                                 b_root, out);

    scatter_kernel<<<N_EDGES / 16, 256>>>(edge_index, edge_type, out);
}

// round 8
// speedup vs baseline: 4.1516x; 1.5649x over previous
#include <cuda_runtime.h>
#include <cstdint>
#include <cstddef>

// Problem constants (fixed by the dataset).
#define N_NODES 300000
#define N_EDGES 4000000
#define IC      128
#define OC      64
#define NREL    7
#define NTYPE   4
#define TILE_N  128
#define NBLK    ((N_NODES + TILE_N - 1) / TILE_N)

// Device scratch (static allocation — no cudaMalloc allowed).
__device__ float g_h[(size_t)NREL * N_NODES * OC];   // per-relation transformed features
__device__ int   g_cnt[N_NODES * NREL];
__device__ float g_inv[N_NODES * NREL];

// ---------------------------------------------------------------------------
// Packed f32x2 FMA helpers (sm_103a FFMA2 — 2x scalar FFMA throughput).
// ---------------------------------------------------------------------------
__device__ __forceinline__ unsigned long long fma2(unsigned long long a,
                                                   unsigned long long b,
                                                   unsigned long long c) {
    unsigned long long d;
    asm("fma.rn.f32x2 %0, %1, %2, %3;" : "=l"(d) : "l"(a), "l"(b), "l"(c));
    return d;
}
__device__ __forceinline__ unsigned long long pack2(float lo, float hi) {
    unsigned long long d;
    asm("mov.b64 %0, {%1, %2};" : "=l"(d) : "f"(lo), "f"(hi));
    return d;
}
__device__ __forceinline__ float2 unpack2(unsigned long long v) {
    float lo, hi;
    asm("mov.b64 {%0, %1}, %2;" : "=f"(lo), "=f"(hi) : "l"(v));
    return make_float2(lo, hi);
}

// ---------------------------------------------------------------------------
// Phase 1: per-(dst, relation) edge counts -> 1/max(cnt,1)
// ---------------------------------------------------------------------------
__global__ void zero_cnt_kernel() {
    int i = blockIdx.x * blockDim.x + threadIdx.x;
    if (i < N_NODES * NREL) g_cnt[i] = 0;
}

__global__ void count_kernel(const int* __restrict__ edge_index,
                             const int* __restrict__ edge_type) {
    int e = blockIdx.x * blockDim.x + threadIdx.x;
    if (e < N_EDGES) {
        int dst = edge_index[N_EDGES + e];
        int rel = edge_type[e];
        atomicAdd(&g_cnt[dst * NREL + rel], 1);
    }
}

__global__ void inv_kernel() {
    int i = blockIdx.x * blockDim.x + threadIdx.x;
    if (i < N_NODES * NREL) {
        int c = g_cnt[i];
        g_inv[i] = 1.0f / (float)(c > 0 ? c : 1);
    }
}

// ---------------------------------------------------------------------------
// Phase 2+3 fused: 11 weight passes over a 128-node x-tile.
//   pass 0..6  : h[r][n][:] = x[n][:] @ W_rel[r]          -> g_h
//   pass 7..10 : out[n][:]  = x[n][:] @ W_root[t] + b[t]  (store iff type==t)
// 128 threads; thread (tx=tid&15, ty=tid>>4) computes 8 nodes x 8 outputs as
// 32 f32x2 accumulators: acc[a][b] = node a, outputs {2b, 2b+1} (outputs
// paired). W loads are natural LDS.128 (no duplication); x is duplicated
// in-register (MOV pair, alu pipe). Per k: 4 LDS.128 + 8 MOV + 32 FFMA2.
// smem: sW = W (32KB), sX = x transposed (64KB) -> 96KB dynamic.
// ---------------------------------------------------------------------------
__global__ void __launch_bounds__(128) fused_gemm_kernel(
        const float* __restrict__ x,
        const int*   __restrict__ node_type,
        const float* __restrict__ W_rel,
        const float* __restrict__ W_root,
        const float* __restrict__ b_root,
        float* __restrict__ out) {
    extern __shared__ char smem_raw[];
    float* sW = (float*)smem_raw;                       // [IC][OC]
    float* sX = (float*)(smem_raw + (size_t)IC * OC * 4); // [IC][TILE_N] transposed

    const int tid = threadIdx.x;
    const int n0  = blockIdx.x * TILE_N;
    const int tx  = tid & 15;     // node group: nodes tx*8 .. tx*8+7
    const int ty  = tid >> 4;     // output group: outs ty*8 .. ty*8+7

    // ---- stage x transposed (thread t = node t; conflict-free STS) ----
    {
        const bool valid = (n0 + tid) < N_NODES;
        const float4* xrow = (const float4*)(x + (size_t)(n0 + tid) * IC);
#pragma unroll
        for (int j = 0; j < 32; j++) {
            float4 v = valid ? xrow[j] : make_float4(0.f, 0.f, 0.f, 0.f);
            int c = j * 4;
            sX[(c + 0) * TILE_N + tid] = v.x;
            sX[(c + 1) * TILE_N + tid] = v.y;
            sX[(c + 2) * TILE_N + tid] = v.z;
            sX[(c + 3) * TILE_N + tid] = v.w;
        }
    }

    // preload node types for the root passes' masked stores
    int ntv[8];
#pragma unroll
    for (int i = 0; i < 8; i++) {
        int n = n0 + tx * 8 + i;
        ntv[i] = (n < N_NODES) ? node_type[n] : -1;
    }

    for (int pass = 0; pass < NREL + NTYPE; pass++) {
        const float* Wg = (pass < NREL)
            ? (W_rel  + (size_t)pass * IC * OC)
            : (W_root + (size_t)(pass - NREL) * IC * OC);

        __syncthreads();   // previous pass finished reading sW (covers sX stage too)
        {   // stage all IC*OC = 8192 floats = 2048 float4 (16 per thread)
            const float4* Wg4 = (const float4*)Wg;
            float4* sW4 = (float4*)sW;
#pragma unroll
            for (int j = 0; j < 16; j++)
                sW4[j * 128 + tid] = Wg4[j * 128 + tid];
        }
        __syncthreads();

        unsigned long long acc[8][4];
#pragma unroll
        for (int a = 0; a < 8; a++)
#pragma unroll
            for (int b = 0; b < 4; b++) acc[a][b] = 0ULL;

#pragma unroll 2
        for (int k = 0; k < IC; k++) {
            const float4* xr = (const float4*)(sX + k * TILE_N + tx * 8);
            float4 a0 = xr[0], a1 = xr[1];
            const ulonglong2* wr = (const ulonglong2*)(sW + k * OC + ty * 8);
            ulonglong2 w0 = wr[0], w1 = wr[1];

            unsigned long long xd[8];
            xd[0] = pack2(a0.x, a0.x); xd[1] = pack2(a0.y, a0.y);
            xd[2] = pack2(a0.z, a0.z); xd[3] = pack2(a0.w, a0.w);
            xd[4] = pack2(a1.x, a1.x); xd[5] = pack2(a1.y, a1.y);
            xd[6] = pack2(a1.z, a1.z); xd[7] = pack2(a1.w, a1.w);
            unsigned long long wq[4] = {w0.x, w0.y, w1.x, w1.y};
#pragma unroll
            for (int a = 0; a < 8; a++)
#pragma unroll
                for (int b = 0; b < 4; b++)
                    acc[a][b] = fma2(xd[a], wq[b], acc[a][b]);
        }

        if (pass < NREL) {
            float* hb = g_h + (size_t)pass * N_NODES * OC;
#pragma unroll
            for (int a = 0; a < 8; a++) {
                int n = n0 + tx * 8 + a;
                if (n < N_NODES) {
                    float2 u0 = unpack2(acc[a][0]);
                    float2 u1 = unpack2(acc[a][1]);
                    float2 u2 = unpack2(acc[a][2]);
                    float2 u3 = unpack2(acc[a][3]);
                    float4* p = (float4*)(hb + (size_t)n * OC + ty * 8);
                    p[0] = make_float4(u0.x, u0.y, u1.x, u1.y);
                    p[1] = make_float4(u2.x, u2.y, u3.x, u3.y);
                }
            }
        } else {
            int t = pass - NREL;
            float4 b0 = *(const float4*)(b_root + t * OC + ty * 8);
            float4 b1 = *(const float4*)(b_root + t * OC + ty * 8 + 4);
#pragma unroll
            for (int a = 0; a < 8; a++) {
                if (ntv[a] == t) {
                    int n = n0 + tx * 8 + a;
                    float2 u0 = unpack2(acc[a][0]);
                    float2 u1 = unpack2(acc[a][1]);
                    float2 u2 = unpack2(acc[a][2]);
                    float2 u3 = unpack2(acc[a][3]);
                    float4* p = (float4*)(out + (size_t)n * OC + ty * 8);
                    p[0] = make_float4(u0.x + b0.x, u0.y + b0.y,
                                       u1.x + b0.z, u1.y + b0.w);
                    p[1] = make_float4(u2.x + b1.x, u2.y + b1.y,
                                       u3.x + b1.z, u3.y + b1.w);
                }
            }
        }
    }
}

// ---------------------------------------------------------------------------
// Phase 4: scatter  out[dst] += h[rel][src] * inv[dst*R+rel]
// 16 threads per edge, each commits one float4 via the sm_90+ vector atomic.
// ---------------------------------------------------------------------------
__global__ void __launch_bounds__(256) scatter_kernel(const int* __restrict__ edge_index,
                                                      const int* __restrict__ edge_type,
                                                      float* __restrict__ out) {
    const int tid  = threadIdx.x;
    const int e    = blockIdx.x * 16 + (tid >> 4);   // N_EDGES % 16 == 0
    const int lane = tid & 15;

    const int src = edge_index[e];
    const int dst = edge_index[N_EDGES + e];
    const int rel = edge_type[e];
    const float w = g_inv[dst * NREL + rel];

    const float4* hp = (const float4*)(g_h + ((size_t)rel * N_NODES + src) * OC);
    float4 v = hp[lane];
    v.x *= w; v.y *= w; v.z *= w; v.w *= w;

    float4* op = (float4*)(out + (size_t)dst * OC + lane * 4);
#if __CUDA_ARCH__ >= 900
    atomicAdd(op, v);                 // RED.ADD.V4.F32
#else
    float* os = (float*)op;
    atomicAdd(os + 0, v.x);
    atomicAdd(os + 1, v.y);
    atomicAdd(os + 2, v.z);
    atomicAdd(os + 3, v.w);
#endif
}

// ---------------------------------------------------------------------------
// Launch
// ---------------------------------------------------------------------------
extern "C" void kernel_launch(void* const* d_in, const int* in_sizes, int n_in,
                              void* d_out, int out_size) {
    const float* x          = (const float*)d_in[0];
    const int*   edge_index = (const int*)d_in[1];
    const int*   edge_type  = (const int*)d_in[2];
    const int*   node_type  = (const int*)d_in[3];
    const float* W_rel      = (const float*)d_in[4];
    const float* W_root     = (const float*)d_in[5];
    const float* b_root     = (const float*)d_in[6];
    float*       out        = (float*)d_out;

    const int nr = N_NODES * NREL;
    zero_cnt_kernel<<<(nr + 255) / 256, 256>>>();
    count_kernel<<<(N_EDGES + 255) / 256, 256>>>(edge_index, edge_type);
    inv_kernel<<<(nr + 255) / 256, 256>>>();

    const size_t fused_smem = (size_t)IC * OC * 4 + (size_t)IC * TILE_N * 4; // 96KB
    (void)cudaFuncSetAttribute(fused_gemm_kernel,
                               cudaFuncAttributeMaxDynamicSharedMemorySize,
                               (int)fused_smem);
    fused_gemm_kernel<<<NBLK, 128, fused_smem>>>(x, node_type, W_rel, W_root,
                                                 b_root, out);

    scatter_kernel<<<N_EDGES / 16, 256>>>(edge_index, edge_type, out);
}

// round 11
// speedup vs baseline: 6.8651x; 1.6536x over previous
#include <cuda_runtime.h>
#include <cuda_bf16.h>
#include <cstdint>
#include <cstddef>

// Problem constants (fixed by the dataset).
#define N_NODES 300000
#define N_EDGES 4000000
#define IC      128
#define OC      64
#define NREL    7
#define NTYPE   4
#define NPASS   (NREL + NTYPE)
#define TILE_M  128
#define NBLK    ((N_NODES + TILE_M - 1) / TILE_M)

// Device scratch (static allocation — no cudaMalloc allowed).
__device__ float g_h[(size_t)NREL * N_NODES * OC];
__device__ int   g_cnt[N_NODES * NREL];
__device__ float g_inv[N_NODES * NREL];

// ---------------------------------------------------------------------------
// Phase 1: per-(dst, relation) edge counts -> 1/max(cnt,1)
// ---------------------------------------------------------------------------
__global__ void zero_cnt_kernel() {
    int i = blockIdx.x * blockDim.x + threadIdx.x;
    if (i < N_NODES * NREL) g_cnt[i] = 0;
}
__global__ void count_kernel(const int* __restrict__ edge_index,
                             const int* __restrict__ edge_type) {
    int e = blockIdx.x * blockDim.x + threadIdx.x;
    if (e < N_EDGES) {
        int dst = edge_index[N_EDGES + e];
        int rel = edge_type[e];
        atomicAdd(&g_cnt[dst * NREL + rel], 1);
    }
}
__global__ void inv_kernel() {
    int i = blockIdx.x * blockDim.x + threadIdx.x;
    if (i < N_NODES * NREL) {
        int c = g_cnt[i];
        g_inv[i] = 1.0f / (float)(c > 0 ? c : 1);
    }
}

// ---------------------------------------------------------------------------
// HMMA helpers (baseline PTX — supported on plain sm_103 target).
// ---------------------------------------------------------------------------
__device__ __forceinline__ uint32_t smem_u32(const void* p) {
    uint32_t a;
    asm("{ .reg .u64 t; cvta.to.shared.u64 t, %1; cvt.u32.u64 %0, t; }"
        : "=r"(a) : "l"(p));
    return a;
}
__device__ __forceinline__ void ldsm_x4(uint32_t* r, uint32_t addr) {
    asm volatile("ldmatrix.sync.aligned.m8n8.x4.shared.b16 {%0,%1,%2,%3}, [%4];"
                 : "=r"(r[0]), "=r"(r[1]), "=r"(r[2]), "=r"(r[3]) : "r"(addr));
}
__device__ __forceinline__ void ldsm_x4_t(uint32_t* r, uint32_t addr) {
    asm volatile("ldmatrix.sync.aligned.m8n8.x4.trans.shared.b16 {%0,%1,%2,%3}, [%4];"
                 : "=r"(r[0]), "=r"(r[1]), "=r"(r[2]), "=r"(r[3]) : "r"(addr));
}
__device__ __forceinline__ void mma_bf16(float* c, const uint32_t* a,
                                         const uint32_t* b) {
    asm volatile(
        "mma.sync.aligned.m16n8k16.row.col.f32.bf16.bf16.f32 "
        "{%0,%1,%2,%3}, {%4,%5,%6,%7}, {%8,%9}, {%0,%1,%2,%3};"
        : "+f"(c[0]), "+f"(c[1]), "+f"(c[2]), "+f"(c[3])
        : "r"(a[0]), "r"(a[1]), "r"(a[2]), "r"(a[3]), "r"(b[0]), "r"(b[1]));
}

// smem layout (bf16, padded rows for conflict-free ldmatrix):
//   sXh/sXl: [128][136]  (row = node, col = k)     34816 B each
//   sWh/sWl: [128][72]   (row = k,   col = o)      18432 B each
#define XPITCH 136
#define WPITCH 72
#define OFF_XH 0
#define OFF_XL 34816
#define OFF_WH 69632
#define OFF_WL 88064
#define SMEM_DYN 106496

// ---------------------------------------------------------------------------
// Fused tensor-core GEMM: 11 passes (7 rel -> g_h, 4 root -> out) per
// 128-node tile. bf16 split (hi/lo), fp32 accumulate:
//   D += Ah*Bh + Al*Bh + Ah*Bl
// 256 threads = 8 warps; warp w owns rows [w*16, w*16+16), all 64 outputs.
// ---------------------------------------------------------------------------
__global__ void __launch_bounds__(256) fused_mma_kernel(
        const float* __restrict__ x,
        const int*   __restrict__ node_type,
        const float* __restrict__ W_rel,
        const float* __restrict__ W_root,
        const float* __restrict__ b_root,
        float* __restrict__ out) {
    extern __shared__ char smem_raw[];
    const uint32_t sb = smem_u32(smem_raw);
    __nv_bfloat16* sXh = (__nv_bfloat16*)(smem_raw + OFF_XH);
    __nv_bfloat16* sXl = (__nv_bfloat16*)(smem_raw + OFF_XL);
    __nv_bfloat16* sWh = (__nv_bfloat16*)(smem_raw + OFF_WH);
    __nv_bfloat16* sWl = (__nv_bfloat16*)(smem_raw + OFF_WL);

    const int tid  = threadIdx.x;
    const int warp = tid >> 5;
    const int lane = tid & 31;
    const int n0   = blockIdx.x * TILE_M;

    // ---- stage x hi/lo: thread covers node tid/2, k-half tid%2 ----
    {
        const int row  = tid >> 1;
        const int kb   = (tid & 1) * 64;
        const bool vld = (n0 + row) < N_NODES;
        const float2* xr = (const float2*)(x + (size_t)(n0 + row) * IC + kb);
        __nv_bfloat162* ph = (__nv_bfloat162*)(sXh + row * XPITCH + kb);
        __nv_bfloat162* pl = (__nv_bfloat162*)(sXl + row * XPITCH + kb);
#pragma unroll
        for (int j = 0; j < 32; j++) {
            float2 v = vld ? xr[j] : make_float2(0.f, 0.f);
            __nv_bfloat16 h0 = __float2bfloat16(v.x);
            __nv_bfloat16 h1 = __float2bfloat16(v.y);
            __nv_bfloat16 l0 = __float2bfloat16(v.x - __bfloat162float(h0));
            __nv_bfloat16 l1 = __float2bfloat16(v.y - __bfloat162float(h1));
            ph[j] = __nv_bfloat162(h0, h1);
            pl[j] = __nv_bfloat162(l0, l1);
        }
    }

    // epilogue row/col mapping for this thread
    const int r0 = n0 + warp * 16 + (lane >> 2);   // D rows (r0, r0+8)
    const int r1 = r0 + 8;
    const int cb = (lane & 3) * 2;                 // col offset within 8-tile
    const bool v0 = r0 < N_NODES;
    const bool v1 = r1 < N_NODES;
    const int t0 = v0 ? node_type[r0] : -1;
    const int t1 = v1 ? node_type[r1] : -1;

    // ldmatrix base addresses (byte, shared space)
    const int lrow = (lane & 7) + ((lane >> 3) & 1) * 8;   // row-within-16
    const int lcol8 = (lane >> 4) * 8;                      // 0 or 8
    const uint32_t aBaseH = sb + OFF_XH +
        (uint32_t)((warp * 16 + lrow) * XPITCH + lcol8) * 2;
    const uint32_t aBaseL = aBaseH + (OFF_XL - OFF_XH);
    const uint32_t bBaseH = sb + OFF_WH + (uint32_t)(lrow * WPITCH + lcol8) * 2;
    const uint32_t bBaseL = bBaseH + (OFF_WL - OFF_WH);

    for (int pass = 0; pass < NPASS; pass++) {
        const float* Wg = (pass < NREL)
            ? (W_rel  + (size_t)pass * IC * OC)
            : (W_root + (size_t)(pass - NREL) * IC * OC);

        __syncthreads();   // prior pass done reading sW (pass 0: x staged)
        // stage W hi/lo: 4096 bf16x2 pairs, 16 per thread
#pragma unroll
        for (int j = 0; j < 16; j++) {
            int idx2 = j * 256 + tid;          // pair index
            int i = idx2 * 2;
            int k = i >> 6, o = i & 63;
            float2 w = *(const float2*)(Wg + i);
            __nv_bfloat16 h0 = __float2bfloat16(w.x);
            __nv_bfloat16 h1 = __float2bfloat16(w.y);
            __nv_bfloat16 l0 = __float2bfloat16(w.x - __bfloat162float(h0));
            __nv_bfloat16 l1 = __float2bfloat16(w.y - __bfloat162float(h1));
            *(__nv_bfloat162*)(sWh + k * WPITCH + o) = __nv_bfloat162(h0, h1);
            *(__nv_bfloat162*)(sWl + k * WPITCH + o) = __nv_bfloat162(l0, l1);
        }
        __syncthreads();

        float acc[8][4];
#pragma unroll
        for (int nt = 0; nt < 8; nt++)
#pragma unroll
            for (int q = 0; q < 4; q++) acc[nt][q] = 0.f;

#pragma unroll 2
        for (int kc = 0; kc < 8; kc++) {
            uint32_t ah[4], al[4];
            ldsm_x4(ah, aBaseH + kc * 32);     // 16 bf16 = 32B per k-chunk
            ldsm_x4(al, aBaseL + kc * 32);
#pragma unroll
            for (int p = 0; p < 4; p++) {      // pairs of n-tiles
                uint32_t bh[4], bl[4];
                uint32_t bo = (uint32_t)(kc * 16 * WPITCH + p * 16) * 2;
                ldsm_x4_t(bh, bBaseH + bo);
                ldsm_x4_t(bl, bBaseL + bo);
                mma_bf16(acc[p * 2],     ah, bh);
                mma_bf16(acc[p * 2 + 1], ah, bh + 2);
                mma_bf16(acc[p * 2],     al, bh);
                mma_bf16(acc[p * 2 + 1], al, bh + 2);
                mma_bf16(acc[p * 2],     ah, bl);
                mma_bf16(acc[p * 2 + 1], ah, bl + 2);
            }
        }

        if (pass < NREL) {
            float* hb = g_h + (size_t)pass * N_NODES * OC;
#pragma unroll
            for (int nt = 0; nt < 8; nt++) {
                int c = nt * 8 + cb;
                if (v0) *(float2*)(hb + (size_t)r0 * OC + c) =
                            make_float2(acc[nt][0], acc[nt][1]);
                if (v1) *(float2*)(hb + (size_t)r1 * OC + c) =
                            make_float2(acc[nt][2], acc[nt][3]);
            }
        } else {
            int t = pass - NREL;
            const float* bp = b_root + t * OC;
#pragma unroll
            for (int nt = 0; nt < 8; nt++) {
                int c = nt * 8 + cb;
                if (t0 == t) *(float2*)(out + (size_t)r0 * OC + c) =
                    make_float2(acc[nt][0] + bp[c], acc[nt][1] + bp[c + 1]);
                if (t1 == t) *(float2*)(out + (size_t)r1 * OC + c) =
                    make_float2(acc[nt][2] + bp[c], acc[nt][3] + bp[c + 1]);
            }
        }
    }
}

// ---------------------------------------------------------------------------
// Scatter: out[dst] += h[rel][src] * inv[dst*R+rel]   (vector RED)
// ---------------------------------------------------------------------------
__global__ void __launch_bounds__(256) scatter_kernel(const int* __restrict__ edge_index,
                                                      const int* __restrict__ edge_type,
                                                      float* __restrict__ out) {
    const int tid  = threadIdx.x;
    const int e    = blockIdx.x * 16 + (tid >> 4);   // N_EDGES % 16 == 0
    const int lane = tid & 15;

    const int src = edge_index[e];
    const int dst = edge_index[N_EDGES + e];
    const int rel = edge_type[e];
    const float w = g_inv[dst * NREL + rel];

    const float4* hp = (const float4*)(g_h + ((size_t)rel * N_NODES + src) * OC);
    float4 v = hp[lane];
    v.x *= w; v.y *= w; v.z *= w; v.w *= w;

    float4* op = (float4*)(out + (size_t)dst * OC + lane * 4);
    atomicAdd(op, v);                 // RED.ADD.V4.F32 on sm_90+
}

// ---------------------------------------------------------------------------
// Launch
// ---------------------------------------------------------------------------
extern "C" void kernel_launch(void* const* d_in, const int* in_sizes, int n_in,
                              void* d_out, int out_size) {
    const float* x          = (const float*)d_in[0];
    const int*   edge_index = (const int*)d_in[1];
    const int*   edge_type  = (const int*)d_in[2];
    const int*   node_type  = (const int*)d_in[3];
    const float* W_rel      = (const float*)d_in[4];
    const float* W_root     = (const float*)d_in[5];
    const float* b_root     = (const float*)d_in[6];
    float*       out        = (float*)d_out;

    const int nr = N_NODES * NREL;
    zero_cnt_kernel<<<(nr + 255) / 256, 256>>>();
    count_kernel<<<(N_EDGES + 255) / 256, 256>>>(edge_index, edge_type);
    inv_kernel<<<(nr + 255) / 256, 256>>>();

    (void)cudaFuncSetAttribute(fused_mma_kernel,
                               cudaFuncAttributeMaxDynamicSharedMemorySize,
                               SMEM_DYN);
    fused_mma_kernel<<<NBLK, 256, SMEM_DYN>>>(x, node_type, W_rel, W_root,
                                              b_root, out);

    scatter_kernel<<<N_EDGES / 16, 256>>>(edge_index, edge_type, out);
}

// round 12
// speedup vs baseline: 7.2527x; 1.0565x over previous
#include <cuda_runtime.h>
#include <cuda_bf16.h>
#include <cstdint>
#include <cstddef>

// Problem constants (fixed by the dataset).
#define N_NODES 300000
#define N_EDGES 4000000
#define IC      128
#define OC      64
#define NREL    7
#define NTYPE   4
#define NPASS   (NREL + NTYPE)
#define TILE_M  256
#define NBLK    ((N_NODES + TILE_M - 1) / TILE_M)

// Device scratch (static allocation — no cudaMalloc allowed).
__device__ float g_h[(size_t)NREL * N_NODES * OC];
__device__ int   g_cnt[N_NODES * NREL];
__device__ float g_inv[N_NODES * NREL];

// ---------------------------------------------------------------------------
// Phase 1: per-(dst, relation) edge counts -> 1/max(cnt,1)
// ---------------------------------------------------------------------------
__global__ void zero_cnt_kernel() {
    int i = blockIdx.x * blockDim.x + threadIdx.x;
    if (i < N_NODES * NREL) g_cnt[i] = 0;
}
__global__ void count_kernel(const int* __restrict__ edge_index,
                             const int* __restrict__ edge_type) {
    int e = blockIdx.x * blockDim.x + threadIdx.x;
    if (e < N_EDGES) {
        int dst = edge_index[N_EDGES + e];
        int rel = edge_type[e];
        atomicAdd(&g_cnt[dst * NREL + rel], 1);
    }
}
__global__ void inv_kernel() {
    int i = blockIdx.x * blockDim.x + threadIdx.x;
    if (i < N_NODES * NREL) {
        int c = g_cnt[i];
        g_inv[i] = 1.0f / (float)(c > 0 ? c : 1);
    }
}

// ---------------------------------------------------------------------------
// HMMA helpers (baseline PTX — supported on plain sm_103 target).
// ---------------------------------------------------------------------------
__device__ __forceinline__ uint32_t smem_u32(const void* p) {
    uint32_t a;
    asm("{ .reg .u64 t; cvta.to.shared.u64 t, %1; cvt.u32.u64 %0, t; }"
        : "=r"(a) : "l"(p));
    return a;
}
__device__ __forceinline__ void ldsm_x4(uint32_t* r, uint32_t addr) {
    asm volatile("ldmatrix.sync.aligned.m8n8.x4.shared.b16 {%0,%1,%2,%3}, [%4];"
                 : "=r"(r[0]), "=r"(r[1]), "=r"(r[2]), "=r"(r[3]) : "r"(addr));
}
__device__ __forceinline__ void ldsm_x4_t(uint32_t* r, uint32_t addr) {
    asm volatile("ldmatrix.sync.aligned.m8n8.x4.trans.shared.b16 {%0,%1,%2,%3}, [%4];"
                 : "=r"(r[0]), "=r"(r[1]), "=r"(r[2]), "=r"(r[3]) : "r"(addr));
}
__device__ __forceinline__ void mma_bf16(float* c, const uint32_t* a,
                                         const uint32_t* b) {
    asm volatile(
        "mma.sync.aligned.m16n8k16.row.col.f32.bf16.bf16.f32 "
        "{%0,%1,%2,%3}, {%4,%5,%6,%7}, {%8,%9}, {%0,%1,%2,%3};"
        : "+f"(c[0]), "+f"(c[1]), "+f"(c[2]), "+f"(c[3])
        : "r"(a[0]), "r"(a[1]), "r"(a[2]), "r"(a[3]), "r"(b[0]), "r"(b[1]));
}
__device__ __forceinline__ void stg_cs_f2(float* p, float a, float b) {
    asm volatile("st.global.cs.v2.f32 [%0], {%1, %2};" :: "l"(p), "f"(a), "f"(b)
                 : "memory");
}

// smem layout (bf16, padded rows for conflict-free ldmatrix):
//   sXh/sXl: [256][136]  (row = node, col = k)     69632 B each
//   sWh/sWl: [128][72]   (row = k,   col = o)      18432 B each
#define XPITCH 136
#define WPITCH 72
#define OFF_XH 0
#define OFF_XL 69632
#define OFF_WH 139264
#define OFF_WL 157696
#define SMEM_DYN 176128

// ---------------------------------------------------------------------------
// Fused tensor-core GEMM: 11 passes (7 rel -> g_h, 4 root -> out) per
// 256-node tile. bf16 split (hi/lo), fp32 accumulate:
//   D += Ah*Bh + Al*Bh + Ah*Bl
// 256 threads = 8 warps; warp w owns rows [w*32, w*32+32) (two 16-row MMA
// tiles), all 64 outputs. Per k-chunk: 4 A-LDSM + 8 B-LDSM -> 48 HMMA.
// ---------------------------------------------------------------------------
__global__ void __launch_bounds__(256) fused_mma_kernel(
        const float* __restrict__ x,
        const int*   __restrict__ node_type,
        const float* __restrict__ W_rel,
        const float* __restrict__ W_root,
        const float* __restrict__ b_root,
        float* __restrict__ out) {
    extern __shared__ char smem_raw[];
    const uint32_t sb = smem_u32(smem_raw);
    __nv_bfloat16* sXh = (__nv_bfloat16*)(smem_raw + OFF_XH);
    __nv_bfloat16* sXl = (__nv_bfloat16*)(smem_raw + OFF_XL);
    __nv_bfloat16* sWh = (__nv_bfloat16*)(smem_raw + OFF_WH);
    __nv_bfloat16* sWl = (__nv_bfloat16*)(smem_raw + OFF_WL);

    const int tid  = threadIdx.x;
    const int warp = tid >> 5;
    const int lane = tid & 31;
    const int n0   = blockIdx.x * TILE_M;

    // ---- stage x hi/lo: one row (128 floats) per thread ----
    {
        const int row  = tid;
        const bool vld = (n0 + row) < N_NODES;
        const float2* xr = (const float2*)(x + (size_t)(n0 + row) * IC);
        __nv_bfloat162* ph = (__nv_bfloat162*)(sXh + row * XPITCH);
        __nv_bfloat162* pl = (__nv_bfloat162*)(sXl + row * XPITCH);
#pragma unroll
        for (int j = 0; j < 64; j++) {
            float2 v = vld ? xr[j] : make_float2(0.f, 0.f);
            __nv_bfloat16 h0 = __float2bfloat16(v.x);
            __nv_bfloat16 h1 = __float2bfloat16(v.y);
            __nv_bfloat16 l0 = __float2bfloat16(v.x - __bfloat162float(h0));
            __nv_bfloat16 l1 = __float2bfloat16(v.y - __bfloat162float(h1));
            ph[j] = __nv_bfloat162(h0, h1);
            pl[j] = __nv_bfloat162(l0, l1);
        }
    }

    // epilogue row/col mapping (per 16-row sub-tile s: rows rs0, rs0+8)
    const int cb = (lane & 3) * 2;
    int  rr[2][2];  bool vv[2][2];  int tt[2][2];
#pragma unroll
    for (int s = 0; s < 2; s++) {
        rr[s][0] = n0 + warp * 32 + s * 16 + (lane >> 2);
        rr[s][1] = rr[s][0] + 8;
#pragma unroll
        for (int u = 0; u < 2; u++) {
            vv[s][u] = rr[s][u] < N_NODES;
            tt[s][u] = vv[s][u] ? node_type[rr[s][u]] : -1;
        }
    }

    // ldmatrix base addresses (byte, shared space)
    const int lrow  = (lane & 7) + ((lane >> 3) & 1) * 8;
    const int lcol8 = (lane >> 4) * 8;
    uint32_t aBaseH[2], aBaseL[2];
#pragma unroll
    for (int s = 0; s < 2; s++) {
        aBaseH[s] = sb + OFF_XH +
            (uint32_t)((warp * 32 + s * 16 + lrow) * XPITCH + lcol8) * 2;
        aBaseL[s] = aBaseH[s] + (OFF_XL - OFF_XH);
    }
    const uint32_t bBaseH = sb + OFF_WH + (uint32_t)(lrow * WPITCH + lcol8) * 2;
    const uint32_t bBaseL = bBaseH + (OFF_WL - OFF_WH);

    for (int pass = 0; pass < NPASS; pass++) {
        const float* Wg = (pass < NREL)
            ? (W_rel  + (size_t)pass * IC * OC)
            : (W_root + (size_t)(pass - NREL) * IC * OC);

        __syncthreads();   // prior pass done reading sW (pass 0: x staged)
        // stage W hi/lo: 4096 bf16x2 pairs, 16 per thread
#pragma unroll
        for (int j = 0; j < 16; j++) {
            int idx2 = j * 256 + tid;
            int i = idx2 * 2;
            int k = i >> 6, o = i & 63;
            float2 w = *(const float2*)(Wg + i);
            __nv_bfloat16 h0 = __float2bfloat16(w.x);
            __nv_bfloat16 h1 = __float2bfloat16(w.y);
            __nv_bfloat16 l0 = __float2bfloat16(w.x - __bfloat162float(h0));
            __nv_bfloat16 l1 = __float2bfloat16(w.y - __bfloat162float(h1));
            *(__nv_bfloat162*)(sWh + k * WPITCH + o) = __nv_bfloat162(h0, h1);
            *(__nv_bfloat162*)(sWl + k * WPITCH + o) = __nv_bfloat162(l0, l1);
        }
        __syncthreads();

        float acc[2][8][4];
#pragma unroll
        for (int s = 0; s < 2; s++)
#pragma unroll
            for (int nt = 0; nt < 8; nt++)
#pragma unroll
                for (int q = 0; q < 4; q++) acc[s][nt][q] = 0.f;

#pragma unroll 2
        for (int kc = 0; kc < 8; kc++) {
            uint32_t ah[2][4], al[2][4];
#pragma unroll
            for (int s = 0; s < 2; s++) {
                ldsm_x4(ah[s], aBaseH[s] + kc * 32);
                ldsm_x4(al[s], aBaseL[s] + kc * 32);
            }
#pragma unroll
            for (int p = 0; p < 4; p++) {
                uint32_t bh[4], bl[4];
                uint32_t bo = (uint32_t)(kc * 16 * WPITCH + p * 16) * 2;
                ldsm_x4_t(bh, bBaseH + bo);
                ldsm_x4_t(bl, bBaseL + bo);
#pragma unroll
                for (int s = 0; s < 2; s++) {
                    mma_bf16(acc[s][p * 2],     ah[s], bh);
                    mma_bf16(acc[s][p * 2 + 1], ah[s], bh + 2);
                    mma_bf16(acc[s][p * 2],     al[s], bh);
                    mma_bf16(acc[s][p * 2 + 1], al[s], bh + 2);
                    mma_bf16(acc[s][p * 2],     ah[s], bl);
                    mma_bf16(acc[s][p * 2 + 1], ah[s], bl + 2);
                }
            }
        }

        if (pass < NREL) {
            float* hb = g_h + (size_t)pass * N_NODES * OC;
#pragma unroll
            for (int s = 0; s < 2; s++)
#pragma unroll
                for (int nt = 0; nt < 8; nt++) {
                    int c = nt * 8 + cb;
                    if (vv[s][0])
                        stg_cs_f2(hb + (size_t)rr[s][0] * OC + c,
                                  acc[s][nt][0], acc[s][nt][1]);
                    if (vv[s][1])
                        stg_cs_f2(hb + (size_t)rr[s][1] * OC + c,
                                  acc[s][nt][2], acc[s][nt][3]);
                }
        } else {
            int t = pass - NREL;
            const float* bp = b_root + t * OC;
#pragma unroll
            for (int s = 0; s < 2; s++)
#pragma unroll
                for (int nt = 0; nt < 8; nt++) {
                    int c = nt * 8 + cb;
                    if (tt[s][0] == t)
                        *(float2*)(out + (size_t)rr[s][0] * OC + c) =
                            make_float2(acc[s][nt][0] + bp[c],
                                        acc[s][nt][1] + bp[c + 1]);
                    if (tt[s][1] == t)
                        *(float2*)(out + (size_t)rr[s][1] * OC + c) =
                            make_float2(acc[s][nt][2] + bp[c],
                                        acc[s][nt][3] + bp[c + 1]);
                }
        }
    }
}

// ---------------------------------------------------------------------------
// Scatter: out[dst] += h[rel][src] * inv[dst*R+rel]   (vector RED)
// h gathered with streaming loads (one-shot 537MB stream; keep out in L2).
// ---------------------------------------------------------------------------
__global__ void __launch_bounds__(256) scatter_kernel(const int* __restrict__ edge_index,
                                                      const int* __restrict__ edge_type,
                                                      float* __restrict__ out) {
    const int tid  = threadIdx.x;
    const int e    = blockIdx.x * 16 + (tid >> 4);   // N_EDGES % 16 == 0
    const int lane = tid & 15;

    const int src = edge_index[e];
    const int dst = edge_index[N_EDGES + e];
    const int rel = edge_type[e];
    const float w = g_inv[dst * NREL + rel];

    const float4* hp = (const float4*)(g_h + ((size_t)rel * N_NODES + src) * OC);
    float4 v = __ldcs(hp + lane);
    v.x *= w; v.y *= w; v.z *= w; v.w *= w;

    float4* op = (float4*)(out + (size_t)dst * OC + lane * 4);
    atomicAdd(op, v);                 // RED.ADD.V4.F32 on sm_90+
}

// ---------------------------------------------------------------------------
// Launch
// ---------------------------------------------------------------------------
extern "C" void kernel_launch(void* const* d_in, const int* in_sizes, int n_in,
                              void* d_out, int out_size) {
    const float* x          = (const float*)d_in[0];
    const int*   edge_index = (const int*)d_in[1];
    const int*   edge_type  = (const int*)d_in[2];
    const int*   node_type  = (const int*)d_in[3];
    const float* W_rel      = (const float*)d_in[4];
    const float* W_root     = (const float*)d_in[5];
    const float* b_root     = (const float*)d_in[6];
    float*       out        = (float*)d_out;

    const int nr = N_NODES * NREL;
    zero_cnt_kernel<<<(nr + 255) / 256, 256>>>();
    count_kernel<<<(N_EDGES + 255) / 256, 256>>>(edge_index, edge_type);
    inv_kernel<<<(nr + 255) / 256, 256>>>();

    (void)cudaFuncSetAttribute(fused_mma_kernel,
                               cudaFuncAttributeMaxDynamicSharedMemorySize,
                               SMEM_DYN);
    fused_mma_kernel<<<NBLK, 256, SMEM_DYN>>>(x, node_type, W_rel, W_root,
                                              b_root, out);

    scatter_kernel<<<N_EDGES / 16, 256>>>(edge_index, edge_type, out);
}

// round 13
// speedup vs baseline: 7.4603x; 1.0286x over previous
#include <cuda_runtime.h>
#include <cuda_bf16.h>
#include <cstdint>
#include <cstddef>

// Problem constants (fixed by the dataset).
#define N_NODES 300000
#define N_EDGES 4000000
#define IC      128
#define OC      64
#define NREL    7
#define NTYPE   4
#define NPASS   (NREL + NTYPE)
#define TILE_M  256
#define NBLK    ((N_NODES + TILE_M - 1) / TILE_M)

// Device scratch (static allocation — no cudaMalloc allowed).
__device__ float g_h[(size_t)NREL * N_NODES * OC];
__device__ int   g_cnt[N_NODES * NREL];
__device__ float g_inv[N_NODES * NREL];
__device__ __nv_bfloat16 g_wh[NPASS * IC * OC];   // pre-split weights (hi)
__device__ __nv_bfloat16 g_wl[NPASS * IC * OC];   // pre-split weights (lo)

// ---------------------------------------------------------------------------
// Phase 1: per-(dst, relation) edge counts -> 1/max(cnt,1); W pre-split.
// ---------------------------------------------------------------------------
__global__ void zero_cnt_kernel() {
    int i = blockIdx.x * blockDim.x + threadIdx.x;
    if (i < N_NODES * NREL) g_cnt[i] = 0;
}
__global__ void count_kernel(const int* __restrict__ edge_index,
                             const int* __restrict__ edge_type) {
    int e = blockIdx.x * blockDim.x + threadIdx.x;
    if (e < N_EDGES) {
        int dst = edge_index[N_EDGES + e];
        int rel = edge_type[e];
        atomicAdd(&g_cnt[dst * NREL + rel], 1);
    }
}
__global__ void inv_kernel() {
    int i = blockIdx.x * blockDim.x + threadIdx.x;
    if (i < N_NODES * NREL) {
        int c = g_cnt[i];
        g_inv[i] = 1.0f / (float)(c > 0 ? c : 1);
    }
}
__global__ void conv_w_kernel(const float* __restrict__ W_rel,
                              const float* __restrict__ W_root) {
    int i = blockIdx.x * blockDim.x + threadIdx.x;
    if (i < NPASS * IC * OC) {
        float w = (i < NREL * IC * OC) ? W_rel[i] : W_root[i - NREL * IC * OC];
        __nv_bfloat16 h = __float2bfloat16(w);
        g_wh[i] = h;
        g_wl[i] = __float2bfloat16(w - __bfloat162float(h));
    }
}

// ---------------------------------------------------------------------------
// HMMA / cp.async helpers (baseline PTX — supported on plain sm_103 target).
// ---------------------------------------------------------------------------
__device__ __forceinline__ uint32_t smem_u32(const void* p) {
    uint32_t a;
    asm("{ .reg .u64 t; cvta.to.shared.u64 t, %1; cvt.u32.u64 %0, t; }"
        : "=r"(a) : "l"(p));
    return a;
}
__device__ __forceinline__ void ldsm_x4(uint32_t* r, uint32_t addr) {
    asm volatile("ldmatrix.sync.aligned.m8n8.x4.shared.b16 {%0,%1,%2,%3}, [%4];"
                 : "=r"(r[0]), "=r"(r[1]), "=r"(r[2]), "=r"(r[3]) : "r"(addr));
}
__device__ __forceinline__ void ldsm_x4_t(uint32_t* r, uint32_t addr) {
    asm volatile("ldmatrix.sync.aligned.m8n8.x4.trans.shared.b16 {%0,%1,%2,%3}, [%4];"
                 : "=r"(r[0]), "=r"(r[1]), "=r"(r[2]), "=r"(r[3]) : "r"(addr));
}
__device__ __forceinline__ void mma_bf16(float* c, const uint32_t* a,
                                         const uint32_t* b) {
    asm volatile(
        "mma.sync.aligned.m16n8k16.row.col.f32.bf16.bf16.f32 "
        "{%0,%1,%2,%3}, {%4,%5,%6,%7}, {%8,%9}, {%0,%1,%2,%3};"
        : "+f"(c[0]), "+f"(c[1]), "+f"(c[2]), "+f"(c[3])
        : "r"(a[0]), "r"(a[1]), "r"(a[2]), "r"(a[3]), "r"(b[0]), "r"(b[1]));
}
__device__ __forceinline__ void stg_cs_f2(float* p, float a, float b) {
    asm volatile("st.global.cs.v2.f32 [%0], {%1, %2};" :: "l"(p), "f"(a), "f"(b)
                 : "memory");
}
__device__ __forceinline__ void cp_async16(uint32_t dst, const void* src) {
    asm volatile("cp.async.ca.shared.global [%0], [%1], 16;"
                 :: "r"(dst), "l"(src) : "memory");
}
__device__ __forceinline__ void cp_commit() {
    asm volatile("cp.async.commit_group;" ::: "memory");
}
__device__ __forceinline__ void cp_wait1() {
    asm volatile("cp.async.wait_group 1;" ::: "memory");
}
__device__ __forceinline__ void cp_wait0() {
    asm volatile("cp.async.wait_group 0;" ::: "memory");
}

// smem layout (bf16, padded rows for conflict-free ldmatrix):
//   sXh/sXl: [256][136]  (row = node, col = k)        69632 B each
//   W double buffer: 2 x { Wh [128][72], Wl [128][72] } = 2 x 36864 B
#define XPITCH 136
#define WPITCH 72
#define OFF_XH 0
#define OFF_XL 69632
#define OFF_WB 139264
#define WBUF_BYTES 36864
#define WHALF 18432
#define SMEM_DYN (139264 + 2 * WBUF_BYTES)   // 212992

// stage pass's W (hi+lo) into buffer `buf` via cp.async (8 x 16B per thread)
__device__ __forceinline__ void stage_w_async(uint32_t sb, int buf, int pass,
                                              int tid) {
    const uint32_t wbase = sb + OFF_WB + buf * WBUF_BYTES;
    const __nv_bfloat16* srcs[2] = { g_wh + (size_t)pass * IC * OC,
                                     g_wl + (size_t)pass * IC * OC };
#pragma unroll
    for (int j = 0; j < 8; j++) {
        int i    = j * 256 + tid;      // 0..2047
        int half = i >> 10;            // 0 = hi, 1 = lo
        int rem  = i & 1023;
        int k    = rem >> 3;
        int c8   = rem & 7;            // 16B chunk within row
        const void* src = srcs[half] + k * 64 + c8 * 8;
        uint32_t dst = wbase + half * WHALF + (uint32_t)(k * WPITCH + c8 * 8) * 2;
        cp_async16(dst, src);
    }
}

// ---------------------------------------------------------------------------
// Fused tensor-core GEMM: 11 passes (7 rel -> g_h, 4 root -> out) per
// 256-node tile. bf16 split (hi/lo), fp32 accumulate:
//   D += Ah*Bh + Al*Bh + Ah*Bl   (products issued group-wise to break chains)
// W staging double-buffered via cp.async, overlapped with the MMA loop.
// ---------------------------------------------------------------------------
__global__ void __launch_bounds__(256) fused_mma_kernel(
        const float* __restrict__ x,
        const int*   __restrict__ node_type,
        const float* __restrict__ b_root,
        float* __restrict__ out) {
    extern __shared__ char smem_raw[];
    const uint32_t sb = smem_u32(smem_raw);
    __nv_bfloat16* sXh = (__nv_bfloat16*)(smem_raw + OFF_XH);
    __nv_bfloat16* sXl = (__nv_bfloat16*)(smem_raw + OFF_XL);

    const int tid  = threadIdx.x;
    const int warp = tid >> 5;
    const int lane = tid & 31;
    const int n0   = blockIdx.x * TILE_M;

    // prologue: start W stream for pass 0
    stage_w_async(sb, 0, 0, tid);
    cp_commit();

    // ---- stage x hi/lo: one row (128 floats) per thread ----
    {
        const int row  = tid;
        const bool vld = (n0 + row) < N_NODES;
        const float2* xr = (const float2*)(x + (size_t)(n0 + row) * IC);
        __nv_bfloat162* ph = (__nv_bfloat162*)(sXh + row * XPITCH);
        __nv_bfloat162* pl = (__nv_bfloat162*)(sXl + row * XPITCH);
#pragma unroll
        for (int j = 0; j < 64; j++) {
            float2 v = vld ? xr[j] : make_float2(0.f, 0.f);
            __nv_bfloat16 h0 = __float2bfloat16(v.x);
            __nv_bfloat16 h1 = __float2bfloat16(v.y);
            __nv_bfloat16 l0 = __float2bfloat16(v.x - __bfloat162float(h0));
            __nv_bfloat16 l1 = __float2bfloat16(v.y - __bfloat162float(h1));
            ph[j] = __nv_bfloat162(h0, h1);
            pl[j] = __nv_bfloat162(l0, l1);
        }
    }

    // epilogue row/col mapping (per 16-row sub-tile s: rows rs0, rs0+8)
    const int cb = (lane & 3) * 2;
    int  rr[2][2];  bool vv[2][2];  int tt[2][2];
#pragma unroll
    for (int s = 0; s < 2; s++) {
        rr[s][0] = n0 + warp * 32 + s * 16 + (lane >> 2);
        rr[s][1] = rr[s][0] + 8;
#pragma unroll
        for (int u = 0; u < 2; u++) {
            vv[s][u] = rr[s][u] < N_NODES;
            tt[s][u] = vv[s][u] ? node_type[rr[s][u]] : -1;
        }
    }

    // ldmatrix base addresses (byte, shared space)
    const int lrow  = (lane & 7) + ((lane >> 3) & 1) * 8;
    const int lcol8 = (lane >> 4) * 8;
    uint32_t aBaseH[2], aBaseL[2];
#pragma unroll
    for (int s = 0; s < 2; s++) {
        aBaseH[s] = sb + OFF_XH +
            (uint32_t)((warp * 32 + s * 16 + lrow) * XPITCH + lcol8) * 2;
        aBaseL[s] = aBaseH[s] + (OFF_XL - OFF_XH);
    }
    const uint32_t bOff = (uint32_t)(lrow * WPITCH + lcol8) * 2;

    for (int pass = 0; pass < NPASS; pass++) {
        __syncthreads();   // buffer (pass+1)&1 free; pass 0: covers x staging
        if (pass + 1 < NPASS) {
            stage_w_async(sb, (pass + 1) & 1, pass + 1, tid);
            cp_commit();
            cp_wait1();    // pass's own group (issued last iter) complete
        } else {
            cp_wait0();
        }
        __syncthreads();   // all threads' copies for `pass` landed

        const uint32_t wbase  = sb + OFF_WB + (pass & 1) * WBUF_BYTES;
        const uint32_t bBaseH = wbase + bOff;
        const uint32_t bBaseL = bBaseH + WHALF;

        float acc[2][8][4];
#pragma unroll
        for (int s = 0; s < 2; s++)
#pragma unroll
            for (int nt = 0; nt < 8; nt++)
#pragma unroll
                for (int q = 0; q < 4; q++) acc[s][nt][q] = 0.f;

#pragma unroll 2
        for (int kc = 0; kc < 8; kc++) {
            uint32_t ah[2][4], al[2][4], bh[4][4], bl[4][4];
#pragma unroll
            for (int s = 0; s < 2; s++) {
                ldsm_x4(ah[s], aBaseH[s] + kc * 32);
                ldsm_x4(al[s], aBaseL[s] + kc * 32);
            }
#pragma unroll
            for (int p = 0; p < 4; p++) {
                uint32_t bo = (uint32_t)(kc * 16 * WPITCH + p * 16) * 2;
                ldsm_x4_t(bh[p], bBaseH + bo);
                ldsm_x4_t(bl[p], bBaseL + bo);
            }
            // product groups issued far apart to break accumulator RAW chains
#pragma unroll
            for (int p = 0; p < 4; p++)
#pragma unroll
                for (int s = 0; s < 2; s++) {
                    mma_bf16(acc[s][p * 2],     ah[s], bh[p]);
                    mma_bf16(acc[s][p * 2 + 1], ah[s], bh[p] + 2);
                }
#pragma unroll
            for (int p = 0; p < 4; p++)
#pragma unroll
                for (int s = 0; s < 2; s++) {
                    mma_bf16(acc[s][p * 2],     al[s], bh[p]);
                    mma_bf16(acc[s][p * 2 + 1], al[s], bh[p] + 2);
                }
#pragma unroll
            for (int p = 0; p < 4; p++)
#pragma unroll
                for (int s = 0; s < 2; s++) {
                    mma_bf16(acc[s][p * 2],     ah[s], bl[p]);
                    mma_bf16(acc[s][p * 2 + 1], ah[s], bl[p] + 2);
                }
        }

        if (pass < NREL) {
            float* hb = g_h + (size_t)pass * N_NODES * OC;
#pragma unroll
            for (int s = 0; s < 2; s++)
#pragma unroll
                for (int nt = 0; nt < 8; nt++) {
                    int c = nt * 8 + cb;
                    if (vv[s][0])
                        stg_cs_f2(hb + (size_t)rr[s][0] * OC + c,
                                  acc[s][nt][0], acc[s][nt][1]);
                    if (vv[s][1])
                        stg_cs_f2(hb + (size_t)rr[s][1] * OC + c,
                                  acc[s][nt][2], acc[s][nt][3]);
                }
        } else {
            int t = pass - NREL;
            const float* bp = b_root + t * OC;
#pragma unroll
            for (int s = 0; s < 2; s++)
#pragma unroll
                for (int nt = 0; nt < 8; nt++) {
                    int c = nt * 8 + cb;
                    if (tt[s][0] == t)
                        *(float2*)(out + (size_t)rr[s][0] * OC + c) =
                            make_float2(acc[s][nt][0] + bp[c],
                                        acc[s][nt][1] + bp[c + 1]);
                    if (tt[s][1] == t)
                        *(float2*)(out + (size_t)rr[s][1] * OC + c) =
                            make_float2(acc[s][nt][2] + bp[c],
                                        acc[s][nt][3] + bp[c + 1]);
                }
        }
    }
}

// ---------------------------------------------------------------------------
// Scatter: out[dst] += h[rel][src] * inv[dst*R+rel]   (vector RED)
// ---------------------------------------------------------------------------
__global__ void __launch_bounds__(256) scatter_kernel(const int* __restrict__ edge_index,
                                                      const int* __restrict__ edge_type,
                                                      float* __restrict__ out) {
    const int tid  = threadIdx.x;
    const int e    = blockIdx.x * 16 + (tid >> 4);   // N_EDGES % 16 == 0
    const int lane = tid & 15;

    const int src = edge_index[e];
    const int dst = edge_index[N_EDGES + e];
    const int rel = edge_type[e];
    const float w = g_inv[dst * NREL + rel];

    const float4* hp = (const float4*)(g_h + ((size_t)rel * N_NODES + src) * OC);
    float4 v = __ldcs(hp + lane);
    v.x *= w; v.y *= w; v.z *= w; v.w *= w;

    float4* op = (float4*)(out + (size_t)dst * OC + lane * 4);
    atomicAdd(op, v);                 // RED.ADD.V4.F32 on sm_90+
}

// ---------------------------------------------------------------------------
// Launch
// ---------------------------------------------------------------------------
extern "C" void kernel_launch(void* const* d_in, const int* in_sizes, int n_in,
                              void* d_out, int out_size) {
    const float* x          = (const float*)d_in[0];
    const int*   edge_index = (const int*)d_in[1];
    const int*   edge_type  = (const int*)d_in[2];
    const int*   node_type  = (const int*)d_in[3];
    const float* W_rel      = (const float*)d_in[4];
    const float* W_root     = (const float*)d_in[5];
    const float* b_root     = (const float*)d_in[6];
    float*       out        = (float*)d_out;

    const int nr = N_NODES * NREL;
    zero_cnt_kernel<<<(nr + 255) / 256, 256>>>();
    count_kernel<<<(N_EDGES + 255) / 256, 256>>>(edge_index, edge_type);
    inv_kernel<<<(nr + 255) / 256, 256>>>();
    conv_w_kernel<<<(NPASS * IC * OC + 255) / 256, 256>>>(W_rel, W_root);

    (void)cudaFuncSetAttribute(fused_mma_kernel,
                               cudaFuncAttributeMaxDynamicSharedMemorySize,
                               SMEM_DYN);
    fused_mma_kernel<<<NBLK, 256, SMEM_DYN>>>(x, node_type, b_root, out);

    scatter_kernel<<<N_EDGES / 16, 256>>>(edge_index, edge_type, out);
}

// round 14
// speedup vs baseline: 7.6275x; 1.0224x over previous
#include <cuda_runtime.h>
#include <cuda_bf16.h>
#include <cuda_fp16.h>
#include <cstdint>
#include <cstddef>

// Problem constants (fixed by the dataset).
#define N_NODES 300000
#define N_EDGES 4000000
#define IC      128
#define OC      64
#define NREL    7
#define NTYPE   4
#define NPASS   (NREL + NTYPE)
#define TILE_M  256
#define NBLK    ((N_NODES + TILE_M - 1) / TILE_M)

// Device scratch (static allocation — no cudaMalloc allowed).
__device__ __half g_h[(size_t)NREL * N_NODES * OC];   // fp16 h (halves traffic)
__device__ int   g_cnt[N_NODES * NREL];
__device__ float g_inv[N_NODES * NREL];
__device__ __nv_bfloat16 g_wh[NPASS * IC * OC];   // pre-split weights (hi)
__device__ __nv_bfloat16 g_wl[NPASS * IC * OC];   // pre-split weights (lo)

// ---------------------------------------------------------------------------
// Phase 1: per-(dst, relation) edge counts -> 1/max(cnt,1); W pre-split.
// ---------------------------------------------------------------------------
__global__ void zero_cnt_kernel() {
    int i = blockIdx.x * blockDim.x + threadIdx.x;
    if (i < N_NODES * NREL) g_cnt[i] = 0;
}
__global__ void count_kernel(const int* __restrict__ edge_index,
                             const int* __restrict__ edge_type) {
    int e = blockIdx.x * blockDim.x + threadIdx.x;
    if (e < N_EDGES) {
        int dst = edge_index[N_EDGES + e];
        int rel = edge_type[e];
        atomicAdd(&g_cnt[dst * NREL + rel], 1);
    }
}
__global__ void inv_kernel() {
    int i = blockIdx.x * blockDim.x + threadIdx.x;
    if (i < N_NODES * NREL) {
        int c = g_cnt[i];
        g_inv[i] = 1.0f / (float)(c > 0 ? c : 1);
    }
}
__global__ void conv_w_kernel(const float* __restrict__ W_rel,
                              const float* __restrict__ W_root) {
    int i = blockIdx.x * blockDim.x + threadIdx.x;
    if (i < NPASS * IC * OC) {
        float w = (i < NREL * IC * OC) ? W_rel[i] : W_root[i - NREL * IC * OC];
        __nv_bfloat16 h = __float2bfloat16(w);
        g_wh[i] = h;
        g_wl[i] = __float2bfloat16(w - __bfloat162float(h));
    }
}

// ---------------------------------------------------------------------------
// HMMA / cp.async helpers (baseline PTX — supported on plain sm_103 target).
// ---------------------------------------------------------------------------
__device__ __forceinline__ uint32_t smem_u32(const void* p) {
    uint32_t a;
    asm("{ .reg .u64 t; cvta.to.shared.u64 t, %1; cvt.u32.u64 %0, t; }"
        : "=r"(a) : "l"(p));
    return a;
}
__device__ __forceinline__ void ldsm_x4(uint32_t* r, uint32_t addr) {
    asm volatile("ldmatrix.sync.aligned.m8n8.x4.shared.b16 {%0,%1,%2,%3}, [%4];"
                 : "=r"(r[0]), "=r"(r[1]), "=r"(r[2]), "=r"(r[3]) : "r"(addr));
}
__device__ __forceinline__ void ldsm_x4_t(uint32_t* r, uint32_t addr) {
    asm volatile("ldmatrix.sync.aligned.m8n8.x4.trans.shared.b16 {%0,%1,%2,%3}, [%4];"
                 : "=r"(r[0]), "=r"(r[1]), "=r"(r[2]), "=r"(r[3]) : "r"(addr));
}
__device__ __forceinline__ void mma_bf16(float* c, const uint32_t* a,
                                         const uint32_t* b) {
    asm volatile(
        "mma.sync.aligned.m16n8k16.row.col.f32.bf16.bf16.f32 "
        "{%0,%1,%2,%3}, {%4,%5,%6,%7}, {%8,%9}, {%0,%1,%2,%3};"
        : "+f"(c[0]), "+f"(c[1]), "+f"(c[2]), "+f"(c[3])
        : "r"(a[0]), "r"(a[1]), "r"(a[2]), "r"(a[3]), "r"(b[0]), "r"(b[1]));
}
__device__ __forceinline__ void stg_cs_u32(void* p, uint32_t v) {
    asm volatile("st.global.cs.b32 [%0], %1;" :: "l"(p), "r"(v) : "memory");
}
__device__ __forceinline__ void cp_async16(uint32_t dst, const void* src) {
    asm volatile("cp.async.ca.shared.global [%0], [%1], 16;"
                 :: "r"(dst), "l"(src) : "memory");
}
__device__ __forceinline__ void cp_commit() {
    asm volatile("cp.async.commit_group;" ::: "memory");
}
__device__ __forceinline__ void cp_wait1() {
    asm volatile("cp.async.wait_group 1;" ::: "memory");
}
__device__ __forceinline__ void cp_wait0() {
    asm volatile("cp.async.wait_group 0;" ::: "memory");
}

// smem layout (bf16, padded rows for conflict-free ldmatrix):
//   sXh/sXl: [256][136]  (row = node, col = k)        69632 B each
//   W double buffer: 2 x { Wh [128][72], Wl [128][72] } = 2 x 36864 B
#define XPITCH 136
#define WPITCH 72
#define OFF_XH 0
#define OFF_XL 69632
#define OFF_WB 139264
#define WBUF_BYTES 36864
#define WHALF 18432
#define SMEM_DYN (139264 + 2 * WBUF_BYTES)   // 212992

// stage pass's W (hi+lo) into buffer `buf` via cp.async (8 x 16B per thread)
__device__ __forceinline__ void stage_w_async(uint32_t sb, int buf, int pass,
                                              int tid) {
    const uint32_t wbase = sb + OFF_WB + buf * WBUF_BYTES;
    const __nv_bfloat16* srcs[2] = { g_wh + (size_t)pass * IC * OC,
                                     g_wl + (size_t)pass * IC * OC };
#pragma unroll
    for (int j = 0; j < 8; j++) {
        int i    = j * 256 + tid;      // 0..2047
        int half = i >> 10;            // 0 = hi, 1 = lo
        int rem  = i & 1023;
        int k    = rem >> 3;
        int c8   = rem & 7;            // 16B chunk within row
        const void* src = srcs[half] + k * 64 + c8 * 8;
        uint32_t dst = wbase + half * WHALF + (uint32_t)(k * WPITCH + c8 * 8) * 2;
        cp_async16(dst, src);
    }
}

// ---------------------------------------------------------------------------
// Fused tensor-core GEMM: 11 passes (7 rel -> g_h fp16, 4 root -> out fp32)
// per 256-node tile. bf16 split (hi/lo), fp32 accumulate:
//   D += Ah*Bh + Al*Bh + Ah*Bl   (products issued group-wise to break chains)
// W staging double-buffered via cp.async, overlapped with the MMA loop.
// ---------------------------------------------------------------------------
__global__ void __launch_bounds__(256) fused_mma_kernel(
        const float* __restrict__ x,
        const int*   __restrict__ node_type,
        const float* __restrict__ b_root,
        float* __restrict__ out) {
    extern __shared__ char smem_raw[];
    const uint32_t sb = smem_u32(smem_raw);
    __nv_bfloat16* sXh = (__nv_bfloat16*)(smem_raw + OFF_XH);
    __nv_bfloat16* sXl = (__nv_bfloat16*)(smem_raw + OFF_XL);

    const int tid  = threadIdx.x;
    const int warp = tid >> 5;
    const int lane = tid & 31;
    const int n0   = blockIdx.x * TILE_M;

    // prologue: start W stream for pass 0
    stage_w_async(sb, 0, 0, tid);
    cp_commit();

    // ---- stage x hi/lo: one row (128 floats) per thread ----
    {
        const int row  = tid;
        const bool vld = (n0 + row) < N_NODES;
        const float2* xr = (const float2*)(x + (size_t)(n0 + row) * IC);
        __nv_bfloat162* ph = (__nv_bfloat162*)(sXh + row * XPITCH);
        __nv_bfloat162* pl = (__nv_bfloat162*)(sXl + row * XPITCH);
#pragma unroll
        for (int j = 0; j < 64; j++) {
            float2 v = vld ? xr[j] : make_float2(0.f, 0.f);
            __nv_bfloat16 h0 = __float2bfloat16(v.x);
            __nv_bfloat16 h1 = __float2bfloat16(v.y);
            __nv_bfloat16 l0 = __float2bfloat16(v.x - __bfloat162float(h0));
            __nv_bfloat16 l1 = __float2bfloat16(v.y - __bfloat162float(h1));
            ph[j] = __nv_bfloat162(h0, h1);
            pl[j] = __nv_bfloat162(l0, l1);
        }
    }

    // epilogue row/col mapping (per 16-row sub-tile s: rows rs0, rs0+8)
    const int cb = (lane & 3) * 2;
    int  rr[2][2];  bool vv[2][2];  int tt[2][2];
#pragma unroll
    for (int s = 0; s < 2; s++) {
        rr[s][0] = n0 + warp * 32 + s * 16 + (lane >> 2);
        rr[s][1] = rr[s][0] + 8;
#pragma unroll
        for (int u = 0; u < 2; u++) {
            vv[s][u] = rr[s][u] < N_NODES;
            tt[s][u] = vv[s][u] ? node_type[rr[s][u]] : -1;
        }
    }

    // ldmatrix base addresses (byte, shared space)
    const int lrow  = (lane & 7) + ((lane >> 3) & 1) * 8;
    const int lcol8 = (lane >> 4) * 8;
    uint32_t aBaseH[2], aBaseL[2];
#pragma unroll
    for (int s = 0; s < 2; s++) {
        aBaseH[s] = sb + OFF_XH +
            (uint32_t)((warp * 32 + s * 16 + lrow) * XPITCH + lcol8) * 2;
        aBaseL[s] = aBaseH[s] + (OFF_XL - OFF_XH);
    }
    const uint32_t bOff = (uint32_t)(lrow * WPITCH + lcol8) * 2;

    for (int pass = 0; pass < NPASS; pass++) {
        __syncthreads();   // buffer (pass+1)&1 free; pass 0: covers x staging
        if (pass + 1 < NPASS) {
            stage_w_async(sb, (pass + 1) & 1, pass + 1, tid);
            cp_commit();
            cp_wait1();    // pass's own group (issued last iter) complete
        } else {
            cp_wait0();
        }
        __syncthreads();   // all threads' copies for `pass` landed

        const uint32_t wbase  = sb + OFF_WB + (pass & 1) * WBUF_BYTES;
        const uint32_t bBaseH = wbase + bOff;
        const uint32_t bBaseL = bBaseH + WHALF;

        float acc[2][8][4];
#pragma unroll
        for (int s = 0; s < 2; s++)
#pragma unroll
            for (int nt = 0; nt < 8; nt++)
#pragma unroll
                for (int q = 0; q < 4; q++) acc[s][nt][q] = 0.f;

#pragma unroll 2
        for (int kc = 0; kc < 8; kc++) {
            uint32_t ah[2][4], al[2][4], bh[4][4], bl[4][4];
#pragma unroll
            for (int s = 0; s < 2; s++) {
                ldsm_x4(ah[s], aBaseH[s] + kc * 32);
                ldsm_x4(al[s], aBaseL[s] + kc * 32);
            }
#pragma unroll
            for (int p = 0; p < 4; p++) {
                uint32_t bo = (uint32_t)(kc * 16 * WPITCH + p * 16) * 2;
                ldsm_x4_t(bh[p], bBaseH + bo);
                ldsm_x4_t(bl[p], bBaseL + bo);
            }
            // product groups issued far apart to break accumulator RAW chains
#pragma unroll
            for (int p = 0; p < 4; p++)
#pragma unroll
                for (int s = 0; s < 2; s++) {
                    mma_bf16(acc[s][p * 2],     ah[s], bh[p]);
                    mma_bf16(acc[s][p * 2 + 1], ah[s], bh[p] + 2);
                }
#pragma unroll
            for (int p = 0; p < 4; p++)
#pragma unroll
                for (int s = 0; s < 2; s++) {
                    mma_bf16(acc[s][p * 2],     al[s], bh[p]);
                    mma_bf16(acc[s][p * 2 + 1], al[s], bh[p] + 2);
                }
#pragma unroll
            for (int p = 0; p < 4; p++)
#pragma unroll
                for (int s = 0; s < 2; s++) {
                    mma_bf16(acc[s][p * 2],     ah[s], bl[p]);
                    mma_bf16(acc[s][p * 2 + 1], ah[s], bl[p] + 2);
                }
        }

        if (pass < NREL) {
            __half* hb = g_h + (size_t)pass * N_NODES * OC;
#pragma unroll
            for (int s = 0; s < 2; s++)
#pragma unroll
                for (int nt = 0; nt < 8; nt++) {
                    int c = nt * 8 + cb;
                    if (vv[s][0]) {
                        __half2 hv = __floats2half2_rn(acc[s][nt][0],
                                                       acc[s][nt][1]);
                        stg_cs_u32(hb + (size_t)rr[s][0] * OC + c,
                                   *(uint32_t*)&hv);
                    }
                    if (vv[s][1]) {
                        __half2 hv = __floats2half2_rn(acc[s][nt][2],
                                                       acc[s][nt][3]);
                        stg_cs_u32(hb + (size_t)rr[s][1] * OC + c,
                                   *(uint32_t*)&hv);
                    }
                }
        } else {
            int t = pass - NREL;
            const float* bp = b_root + t * OC;
#pragma unroll
            for (int s = 0; s < 2; s++)
#pragma unroll
                for (int nt = 0; nt < 8; nt++) {
                    int c = nt * 8 + cb;
                    if (tt[s][0] == t)
                        *(float2*)(out + (size_t)rr[s][0] * OC + c) =
                            make_float2(acc[s][nt][0] + bp[c],
                                        acc[s][nt][1] + bp[c + 1]);
                    if (tt[s][1] == t)
                        *(float2*)(out + (size_t)rr[s][1] * OC + c) =
                            make_float2(acc[s][nt][2] + bp[c],
                                        acc[s][nt][3] + bp[c + 1]);
                }
        }
    }
}

// ---------------------------------------------------------------------------
// Scatter: out[dst] += h[rel][src] * inv[dst*R+rel]   (vector RED)
// h is fp16: lane loads uint2 (4 halves), converts, one RED.v4.f32.
// ---------------------------------------------------------------------------
__global__ void __launch_bounds__(256) scatter_kernel(const int* __restrict__ edge_index,
                                                      const int* __restrict__ edge_type,
                                                      float* __restrict__ out) {
    const int tid  = threadIdx.x;
    const int e    = blockIdx.x * 16 + (tid >> 4);   // N_EDGES % 16 == 0
    const int lane = tid & 15;

    const int src = edge_index[e];
    const int dst = edge_index[N_EDGES + e];
    const int rel = edge_type[e];
    const float w = g_inv[dst * NREL + rel];

    const uint2* hp = (const uint2*)(g_h + ((size_t)rel * N_NODES + src) * OC);
    uint2 raw = __ldcs(hp + lane);
    __half2 ha = *(__half2*)&raw.x;
    __half2 hb = *(__half2*)&raw.y;
    float2 f0 = __half22float2(ha);
    float2 f1 = __half22float2(hb);
    float4 v = make_float4(f0.x * w, f0.y * w, f1.x * w, f1.y * w);

    float4* op = (float4*)(out + (size_t)dst * OC + lane * 4);
    atomicAdd(op, v);                 // RED.ADD.V4.F32 on sm_90+
}

// ---------------------------------------------------------------------------
// Launch
// ---------------------------------------------------------------------------
extern "C" void kernel_launch(void* const* d_in, const int* in_sizes, int n_in,
                              void* d_out, int out_size) {
    const float* x          = (const float*)d_in[0];
    const int*   edge_index = (const int*)d_in[1];
    const int*   edge_type  = (const int*)d_in[2];
    const int*   node_type  = (const int*)d_in[3];
    const float* W_rel      = (const float*)d_in[4];
    const float* W_root     = (const float*)d_in[5];
    const float* b_root     = (const float*)d_in[6];
    float*       out        = (float*)d_out;

    const int nr = N_NODES * NREL;
    zero_cnt_kernel<<<(nr + 255) / 256, 256>>>();
    count_kernel<<<(N_EDGES + 255) / 256, 256>>>(edge_index, edge_type);
    inv_kernel<<<(nr + 255) / 256, 256>>>();
    conv_w_kernel<<<(NPASS * IC * OC + 255) / 256, 256>>>(W_rel, W_root);

    (void)cudaFuncSetAttribute(fused_mma_kernel,
                               cudaFuncAttributeMaxDynamicSharedMemorySize,
                               SMEM_DYN);
    fused_mma_kernel<<<NBLK, 256, SMEM_DYN>>>(x, node_type, b_root, out);

    scatter_kernel<<<N_EDGES / 16, 256>>>(edge_index, edge_type, out);
}

// round 15
// speedup vs baseline: 8.6269x; 1.1310x over previous
#include <cuda_runtime.h>
#include <cuda_bf16.h>
#include <cuda_fp16.h>
#include <cstdint>
#include <cstddef>

// Problem constants (fixed by the dataset).
#define N_NODES 300000
#define N_EDGES 4000000
#define IC      128
#define OC      64
#define NREL    7
#define NTYPE   4
#define NPASS   (NREL + NTYPE)
#define TILE_M  256
#define NBLK    ((N_NODES + TILE_M - 1) / TILE_M)
#define CAP     96      // bucket capacity per dst (max degree ~35 for Poisson(13.3))

// Device scratch (static allocation — no cudaMalloc allowed).
__device__ __half g_h[(size_t)NREL * N_NODES * OC];   // fp16 h
__device__ int      g_cnt[N_NODES * NREL];
__device__ float    g_inv[N_NODES * NREL];
__device__ int      g_deg[N_NODES];
__device__ uint32_t g_bkt[(size_t)N_NODES * CAP];     // packed src|rel<<19
__device__ __nv_bfloat16 g_wh[NPASS * IC * OC];       // pre-split weights (hi)
__device__ __nv_bfloat16 g_wl[NPASS * IC * OC];       // pre-split weights (lo)

// ---------------------------------------------------------------------------
// Phase 1: counts + bucket fill + inv + W pre-split
// ---------------------------------------------------------------------------
__global__ void zero_kernel() {
    int i = blockIdx.x * blockDim.x + threadIdx.x;
    if (i < N_NODES * NREL) g_cnt[i] = 0;
    if (i < N_NODES) g_deg[i] = 0;
}
__global__ void count_fill_kernel(const int* __restrict__ edge_index,
                                  const int* __restrict__ edge_type) {
    int e = blockIdx.x * blockDim.x + threadIdx.x;
    if (e < N_EDGES) {
        int src = edge_index[e];
        int dst = edge_index[N_EDGES + e];
        int rel = edge_type[e];
        atomicAdd(&g_cnt[dst * NREL + rel], 1);
        int slot = atomicAdd(&g_deg[dst], 1);
        if (slot < CAP)
            g_bkt[(size_t)dst * CAP + slot] =
                (uint32_t)src | ((uint32_t)rel << 19);
    }
}
__global__ void inv_kernel() {
    int i = blockIdx.x * blockDim.x + threadIdx.x;
    if (i < N_NODES * NREL) {
        int c = g_cnt[i];
        g_inv[i] = 1.0f / (float)(c > 0 ? c : 1);
    }
}
__global__ void conv_w_kernel(const float* __restrict__ W_rel,
                              const float* __restrict__ W_root) {
    int i = blockIdx.x * blockDim.x + threadIdx.x;
    if (i < NPASS * IC * OC) {
        float w = (i < NREL * IC * OC) ? W_rel[i] : W_root[i - NREL * IC * OC];
        __nv_bfloat16 h = __float2bfloat16(w);
        g_wh[i] = h;
        g_wl[i] = __float2bfloat16(w - __bfloat162float(h));
    }
}

// ---------------------------------------------------------------------------
// HMMA / cp.async helpers (baseline PTX — supported on plain sm_103 target).
// ---------------------------------------------------------------------------
__device__ __forceinline__ uint32_t smem_u32(const void* p) {
    uint32_t a;
    asm("{ .reg .u64 t; cvta.to.shared.u64 t, %1; cvt.u32.u64 %0, t; }"
        : "=r"(a) : "l"(p));
    return a;
}
__device__ __forceinline__ void ldsm_x4(uint32_t* r, uint32_t addr) {
    asm volatile("ldmatrix.sync.aligned.m8n8.x4.shared.b16 {%0,%1,%2,%3}, [%4];"
                 : "=r"(r[0]), "=r"(r[1]), "=r"(r[2]), "=r"(r[3]) : "r"(addr));
}
__device__ __forceinline__ void ldsm_x4_t(uint32_t* r, uint32_t addr) {
    asm volatile("ldmatrix.sync.aligned.m8n8.x4.trans.shared.b16 {%0,%1,%2,%3}, [%4];"
                 : "=r"(r[0]), "=r"(r[1]), "=r"(r[2]), "=r"(r[3]) : "r"(addr));
}
__device__ __forceinline__ void mma_bf16(float* c, const uint32_t* a,
                                         const uint32_t* b) {
    asm volatile(
        "mma.sync.aligned.m16n8k16.row.col.f32.bf16.bf16.f32 "
        "{%0,%1,%2,%3}, {%4,%5,%6,%7}, {%8,%9}, {%0,%1,%2,%3};"
        : "+f"(c[0]), "+f"(c[1]), "+f"(c[2]), "+f"(c[3])
        : "r"(a[0]), "r"(a[1]), "r"(a[2]), "r"(a[3]), "r"(b[0]), "r"(b[1]));
}
__device__ __forceinline__ void stg_cs_u32(void* p, uint32_t v) {
    asm volatile("st.global.cs.b32 [%0], %1;" :: "l"(p), "r"(v) : "memory");
}
__device__ __forceinline__ void cp_async16(uint32_t dst, const void* src) {
    asm volatile("cp.async.ca.shared.global [%0], [%1], 16;"
                 :: "r"(dst), "l"(src) : "memory");
}
__device__ __forceinline__ void cp_commit() {
    asm volatile("cp.async.commit_group;" ::: "memory");
}
__device__ __forceinline__ void cp_wait1() {
    asm volatile("cp.async.wait_group 1;" ::: "memory");
}
__device__ __forceinline__ void cp_wait0() {
    asm volatile("cp.async.wait_group 0;" ::: "memory");
}

// smem layout (bf16, padded rows for conflict-free ldmatrix):
#define XPITCH 136
#define WPITCH 72
#define OFF_XH 0
#define OFF_XL 69632
#define OFF_WB 139264
#define WBUF_BYTES 36864
#define WHALF 18432
#define SMEM_DYN (139264 + 2 * WBUF_BYTES)   // 212992

__device__ __forceinline__ void stage_w_async(uint32_t sb, int buf, int pass,
                                              int tid) {
    const uint32_t wbase = sb + OFF_WB + buf * WBUF_BYTES;
    const __nv_bfloat16* srcs[2] = { g_wh + (size_t)pass * IC * OC,
                                     g_wl + (size_t)pass * IC * OC };
#pragma unroll
    for (int j = 0; j < 8; j++) {
        int i    = j * 256 + tid;
        int half = i >> 10;
        int rem  = i & 1023;
        int k    = rem >> 3;
        int c8   = rem & 7;
        const void* src = srcs[half] + k * 64 + c8 * 8;
        uint32_t dst = wbase + half * WHALF + (uint32_t)(k * WPITCH + c8 * 8) * 2;
        cp_async16(dst, src);
    }
}

// ---------------------------------------------------------------------------
// Fused tensor-core GEMM: 11 passes (7 rel -> g_h fp16, 4 root -> out fp32)
// per 256-node tile. bf16 split (hi/lo), fp32 accumulate.
// ---------------------------------------------------------------------------
__global__ void __launch_bounds__(256) fused_mma_kernel(
        const float* __restrict__ x,
        const int*   __restrict__ node_type,
        const float* __restrict__ b_root,
        float* __restrict__ out) {
    extern __shared__ char smem_raw[];
    const uint32_t sb = smem_u32(smem_raw);
    __nv_bfloat16* sXh = (__nv_bfloat16*)(smem_raw + OFF_XH);
    __nv_bfloat16* sXl = (__nv_bfloat16*)(smem_raw + OFF_XL);

    const int tid  = threadIdx.x;
    const int warp = tid >> 5;
    const int lane = tid & 31;
    const int n0   = blockIdx.x * TILE_M;

    stage_w_async(sb, 0, 0, tid);
    cp_commit();

    {
        const int row  = tid;
        const bool vld = (n0 + row) < N_NODES;
        const float2* xr = (const float2*)(x + (size_t)(n0 + row) * IC);
        __nv_bfloat162* ph = (__nv_bfloat162*)(sXh + row * XPITCH);
        __nv_bfloat162* pl = (__nv_bfloat162*)(sXl + row * XPITCH);
#pragma unroll
        for (int j = 0; j < 64; j++) {
            float2 v = vld ? xr[j] : make_float2(0.f, 0.f);
            __nv_bfloat16 h0 = __float2bfloat16(v.x);
            __nv_bfloat16 h1 = __float2bfloat16(v.y);
            __nv_bfloat16 l0 = __float2bfloat16(v.x - __bfloat162float(h0));
            __nv_bfloat16 l1 = __float2bfloat16(v.y - __bfloat162float(h1));
            ph[j] = __nv_bfloat162(h0, h1);
            pl[j] = __nv_bfloat162(l0, l1);
        }
    }

    const int cb = (lane & 3) * 2;
    int  rr[2][2];  bool vv[2][2];  int tt[2][2];
#pragma unroll
    for (int s = 0; s < 2; s++) {
        rr[s][0] = n0 + warp * 32 + s * 16 + (lane >> 2);
        rr[s][1] = rr[s][0] + 8;
#pragma unroll
        for (int u = 0; u < 2; u++) {
            vv[s][u] = rr[s][u] < N_NODES;
            tt[s][u] = vv[s][u] ? node_type[rr[s][u]] : -1;
        }
    }

    const int lrow  = (lane & 7) + ((lane >> 3) & 1) * 8;
    const int lcol8 = (lane >> 4) * 8;
    uint32_t aBaseH[2], aBaseL[2];
#pragma unroll
    for (int s = 0; s < 2; s++) {
        aBaseH[s] = sb + OFF_XH +
            (uint32_t)((warp * 32 + s * 16 + lrow) * XPITCH + lcol8) * 2;
        aBaseL[s] = aBaseH[s] + (OFF_XL - OFF_XH);
    }
    const uint32_t bOff = (uint32_t)(lrow * WPITCH + lcol8) * 2;

    for (int pass = 0; pass < NPASS; pass++) {
        __syncthreads();
        if (pass + 1 < NPASS) {
            stage_w_async(sb, (pass + 1) & 1, pass + 1, tid);
            cp_commit();
            cp_wait1();
        } else {
            cp_wait0();
        }
        __syncthreads();

        const uint32_t wbase  = sb + OFF_WB + (pass & 1) * WBUF_BYTES;
        const uint32_t bBaseH = wbase + bOff;
        const uint32_t bBaseL = bBaseH + WHALF;

        float acc[2][8][4];
#pragma unroll
        for (int s = 0; s < 2; s++)
#pragma unroll
            for (int nt = 0; nt < 8; nt++)
#pragma unroll
                for (int q = 0; q < 4; q++) acc[s][nt][q] = 0.f;

#pragma unroll 2
        for (int kc = 0; kc < 8; kc++) {
            uint32_t ah[2][4], al[2][4], bh[4][4], bl[4][4];
#pragma unroll
            for (int s = 0; s < 2; s++) {
                ldsm_x4(ah[s], aBaseH[s] + kc * 32);
                ldsm_x4(al[s], aBaseL[s] + kc * 32);
            }
#pragma unroll
            for (int p = 0; p < 4; p++) {
                uint32_t bo = (uint32_t)(kc * 16 * WPITCH + p * 16) * 2;
                ldsm_x4_t(bh[p], bBaseH + bo);
                ldsm_x4_t(bl[p], bBaseL + bo);
            }
#pragma unroll
            for (int p = 0; p < 4; p++)
#pragma unroll
                for (int s = 0; s < 2; s++) {
                    mma_bf16(acc[s][p * 2],     ah[s], bh[p]);
                    mma_bf16(acc[s][p * 2 + 1], ah[s], bh[p] + 2);
                }
#pragma unroll
            for (int p = 0; p < 4; p++)
#pragma unroll
                for (int s = 0; s < 2; s++) {
                    mma_bf16(acc[s][p * 2],     al[s], bh[p]);
                    mma_bf16(acc[s][p * 2 + 1], al[s], bh[p] + 2);
                }
#pragma unroll
            for (int p = 0; p < 4; p++)
#pragma unroll
                for (int s = 0; s < 2; s++) {
                    mma_bf16(acc[s][p * 2],     ah[s], bl[p]);
                    mma_bf16(acc[s][p * 2 + 1], ah[s], bl[p] + 2);
                }
        }

        if (pass < NREL) {
            __half* hb = g_h + (size_t)pass * N_NODES * OC;
#pragma unroll
            for (int s = 0; s < 2; s++)
#pragma unroll
                for (int nt = 0; nt < 8; nt++) {
                    int c = nt * 8 + cb;
                    if (vv[s][0]) {
                        __half2 hv = __floats2half2_rn(acc[s][nt][0],
                                                       acc[s][nt][1]);
                        stg_cs_u32(hb + (size_t)rr[s][0] * OC + c,
                                   *(uint32_t*)&hv);
                    }
                    if (vv[s][1]) {
                        __half2 hv = __floats2half2_rn(acc[s][nt][2],
                                                       acc[s][nt][3]);
                        stg_cs_u32(hb + (size_t)rr[s][1] * OC + c,
                                   *(uint32_t*)&hv);
                    }
                }
        } else {
            int t = pass - NREL;
            const float* bp = b_root + t * OC;
#pragma unroll
            for (int s = 0; s < 2; s++)
#pragma unroll
                for (int nt = 0; nt < 8; nt++) {
                    int c = nt * 8 + cb;
                    if (tt[s][0] == t)
                        *(float2*)(out + (size_t)rr[s][0] * OC + c) =
                            make_float2(acc[s][nt][0] + bp[c],
                                        acc[s][nt][1] + bp[c + 1]);
                    if (tt[s][1] == t)
                        *(float2*)(out + (size_t)rr[s][1] * OC + c) =
                            make_float2(acc[s][nt][2] + bp[c],
                                        acc[s][nt][3] + bp[c + 1]);
                }
        }
    }
}

// ---------------------------------------------------------------------------
// Gather: one warp per dst node. out[dst] += sum_e w_e * h[rel_e][src_e].
// Lane owns 2 output floats (half2 per lane). No atomics; 4-wide batched
// loads for MLP over the random h-row gather.
// ---------------------------------------------------------------------------
__global__ void __launch_bounds__(256) gather_kernel(float* __restrict__ out) {
    const int dst  = (blockIdx.x * 256 + threadIdx.x) >> 5;   // 8 warps/block
    const int lane = threadIdx.x & 31;

    int deg = g_deg[dst];
    if (deg > CAP) deg = CAP;
    if (deg == 0) return;

    const uint32_t* bk = g_bkt + (size_t)dst * CAP;
    const float*    iv = g_inv + dst * NREL;

    float2 acc = make_float2(0.f, 0.f);
    int i = 0;
    for (; i + 4 <= deg; i += 4) {
        uint32_t e0 = bk[i], e1 = bk[i + 1], e2 = bk[i + 2], e3 = bk[i + 3];
        const __half2* p0 = (const __half2*)(g_h +
            ((size_t)(e0 >> 19) * N_NODES + (e0 & 0x7FFFF)) * OC) + lane;
        const __half2* p1 = (const __half2*)(g_h +
            ((size_t)(e1 >> 19) * N_NODES + (e1 & 0x7FFFF)) * OC) + lane;
        const __half2* p2 = (const __half2*)(g_h +
            ((size_t)(e2 >> 19) * N_NODES + (e2 & 0x7FFFF)) * OC) + lane;
        const __half2* p3 = (const __half2*)(g_h +
            ((size_t)(e3 >> 19) * N_NODES + (e3 & 0x7FFFF)) * OC) + lane;
        __half2 h0 = __ldcs(p0), h1 = __ldcs(p1), h2 = __ldcs(p2), h3 = __ldcs(p3);
        float w0 = iv[e0 >> 19], w1 = iv[e1 >> 19];
        float w2 = iv[e2 >> 19], w3 = iv[e3 >> 19];
        float2 f0 = __half22float2(h0), f1 = __half22float2(h1);
        float2 f2 = __half22float2(h2), f3 = __half22float2(h3);
        acc.x += w0 * f0.x + w1 * f1.x + w2 * f2.x + w3 * f3.x;
        acc.y += w0 * f0.y + w1 * f1.y + w2 * f2.y + w3 * f3.y;
    }
    for (; i < deg; i++) {
        uint32_t e = bk[i];
        const __half2* p = (const __half2*)(g_h +
            ((size_t)(e >> 19) * N_NODES + (e & 0x7FFFF)) * OC) + lane;
        float2 f = __half22float2(__ldcs(p));
        float w = iv[e >> 19];
        acc.x += w * f.x;
        acc.y += w * f.y;
    }

    float2* op = (float2*)(out + (size_t)dst * OC) + lane;
    float2 cur = *op;
    *op = make_float2(cur.x + acc.x, cur.y + acc.y);
}

// ---------------------------------------------------------------------------
// Launch
// ---------------------------------------------------------------------------
extern "C" void kernel_launch(void* const* d_in, const int* in_sizes, int n_in,
                              void* d_out, int out_size) {
    const float* x          = (const float*)d_in[0];
    const int*   edge_index = (const int*)d_in[1];
    const int*   edge_type  = (const int*)d_in[2];
    const int*   node_type  = (const int*)d_in[3];
    const float* W_rel      = (const float*)d_in[4];
    const float* W_root     = (const float*)d_in[5];
    const float* b_root     = (const float*)d_in[6];
    float*       out        = (float*)d_out;

    const int nr = N_NODES * NREL;
    zero_kernel<<<(nr + 255) / 256, 256>>>();
    count_fill_kernel<<<(N_EDGES + 255) / 256, 256>>>(edge_index, edge_type);
    inv_kernel<<<(nr + 255) / 256, 256>>>();
    conv_w_kernel<<<(NPASS * IC * OC + 255) / 256, 256>>>(W_rel, W_root);

    (void)cudaFuncSetAttribute(fused_mma_kernel,
                               cudaFuncAttributeMaxDynamicSharedMemorySize,
                               SMEM_DYN);
    fused_mma_kernel<<<NBLK, 256, SMEM_DYN>>>(x, node_type, b_root, out);

    gather_kernel<<<N_NODES / 8, 256>>>(out);
}

// round 16
// speedup vs baseline: 10.5511x; 1.2230x over previous
#include <cuda_runtime.h>
#include <cuda_fp16.h>
#include <cstdint>
#include <cstddef>

// Problem constants (fixed by the dataset).
#define N_NODES 300000
#define N_EDGES 4000000
#define IC      128
#define OC      64
#define NREL    7
#define NTYPE   4
#define NPASS   (NREL + NTYPE)
#define TILE_M  256
#define NBLK    ((N_NODES + TILE_M - 1) / TILE_M)
#define CAP     96      // bucket capacity per dst (max degree ~35 for Poisson(13.3))

// Device scratch (static allocation — no cudaMalloc allowed).
__device__ __half g_h[(size_t)NREL * N_NODES * OC];   // fp16 h
__device__ int      g_cnt[N_NODES * NREL];
__device__ float    g_inv[N_NODES * NREL];
__device__ int      g_deg[N_NODES];
__device__ uint32_t g_bkt[(size_t)N_NODES * CAP];     // packed src|rel<<19
__device__ __half g_wh[NPASS * IC * OC];              // pre-split weights (hi, fp16)
__device__ __half g_wl[NPASS * IC * OC];              // pre-split weights (lo, fp16)

// ---------------------------------------------------------------------------
// Phase 1: counts + bucket fill + inv + W pre-split (fp16 hi/lo)
// ---------------------------------------------------------------------------
__global__ void zero_kernel() {
    int i = blockIdx.x * blockDim.x + threadIdx.x;
    if (i < N_NODES * NREL) g_cnt[i] = 0;
    if (i < N_NODES) g_deg[i] = 0;
}
__global__ void count_fill_kernel(const int* __restrict__ edge_index,
                                  const int* __restrict__ edge_type) {
    int e = blockIdx.x * blockDim.x + threadIdx.x;
    if (e < N_EDGES) {
        int src = edge_index[e];
        int dst = edge_index[N_EDGES + e];
        int rel = edge_type[e];
        atomicAdd(&g_cnt[dst * NREL + rel], 1);
        int slot = atomicAdd(&g_deg[dst], 1);
        if (slot < CAP)
            g_bkt[(size_t)dst * CAP + slot] =
                (uint32_t)src | ((uint32_t)rel << 19);
    }
}
__global__ void inv_kernel() {
    int i = blockIdx.x * blockDim.x + threadIdx.x;
    if (i < N_NODES * NREL) {
        int c = g_cnt[i];
        g_inv[i] = 1.0f / (float)(c > 0 ? c : 1);
    }
}
__global__ void conv_w_kernel(const float* __restrict__ W_rel,
                              const float* __restrict__ W_root) {
    int i = blockIdx.x * blockDim.x + threadIdx.x;
    if (i < NPASS * IC * OC) {
        float w = (i < NREL * IC * OC) ? W_rel[i] : W_root[i - NREL * IC * OC];
        __half h = __float2half_rn(w);
        g_wh[i] = h;
        g_wl[i] = __float2half_rn(w - __half2float(h));
    }
}

// ---------------------------------------------------------------------------
// HMMA / cp.async helpers (baseline PTX — supported on plain sm_103 target).
// ---------------------------------------------------------------------------
__device__ __forceinline__ uint32_t smem_u32(const void* p) {
    uint32_t a;
    asm("{ .reg .u64 t; cvta.to.shared.u64 t, %1; cvt.u32.u64 %0, t; }"
        : "=r"(a) : "l"(p));
    return a;
}
__device__ __forceinline__ void ldsm_x4(uint32_t* r, uint32_t addr) {
    asm volatile("ldmatrix.sync.aligned.m8n8.x4.shared.b16 {%0,%1,%2,%3}, [%4];"
                 : "=r"(r[0]), "=r"(r[1]), "=r"(r[2]), "=r"(r[3]) : "r"(addr));
}
__device__ __forceinline__ void ldsm_x4_t(uint32_t* r, uint32_t addr) {
    asm volatile("ldmatrix.sync.aligned.m8n8.x4.trans.shared.b16 {%0,%1,%2,%3}, [%4];"
                 : "=r"(r[0]), "=r"(r[1]), "=r"(r[2]), "=r"(r[3]) : "r"(addr));
}
__device__ __forceinline__ void mma_f16(float* c, const uint32_t* a,
                                        const uint32_t* b) {
    asm volatile(
        "mma.sync.aligned.m16n8k16.row.col.f32.f16.f16.f32 "
        "{%0,%1,%2,%3}, {%4,%5,%6,%7}, {%8,%9}, {%0,%1,%2,%3};"
        : "+f"(c[0]), "+f"(c[1]), "+f"(c[2]), "+f"(c[3])
        : "r"(a[0]), "r"(a[1]), "r"(a[2]), "r"(a[3]), "r"(b[0]), "r"(b[1]));
}
__device__ __forceinline__ void stg_cs_u32(void* p, uint32_t v) {
    asm volatile("st.global.cs.b32 [%0], %1;" :: "l"(p), "r"(v) : "memory");
}
__device__ __forceinline__ void cp_async16(uint32_t dst, const void* src) {
    asm volatile("cp.async.ca.shared.global [%0], [%1], 16;"
                 :: "r"(dst), "l"(src) : "memory");
}
__device__ __forceinline__ void cp_commit() {
    asm volatile("cp.async.commit_group;" ::: "memory");
}
__device__ __forceinline__ void cp_wait0() {
    asm volatile("cp.async.wait_group 0;" ::: "memory");
}

// smem layout (fp16, padded rows for conflict-free ldmatrix):
//   sX: [256][136]   (row = node, col = k)   69632 B
//   W:  { Wh [128][72], Wl [128][72] }       36864 B (single buffer)
// total 106496 B -> 2 CTAs/SM.
#define XPITCH 136
#define WPITCH 72
#define OFF_X  0
#define OFF_W  69632
#define WHALF  18432
#define SMEM_DYN (69632 + 36864)

// stage pass's W (hi+lo) into smem via cp.async (8 x 16B per thread)
__device__ __forceinline__ void stage_w_async(uint32_t sb, int pass, int tid) {
    const uint32_t wbase = sb + OFF_W;
    const __half* srcs[2] = { g_wh + (size_t)pass * IC * OC,
                              g_wl + (size_t)pass * IC * OC };
#pragma unroll
    for (int j = 0; j < 8; j++) {
        int i    = j * 256 + tid;      // 0..2047
        int half = i >> 10;            // 0 = hi, 1 = lo
        int rem  = i & 1023;
        int k    = rem >> 3;
        int c8   = rem & 7;            // 16B chunk within row
        const void* src = srcs[half] + k * 64 + c8 * 8;
        uint32_t dst = wbase + half * WHALF + (uint32_t)(k * WPITCH + c8 * 8) * 2;
        cp_async16(dst, src);
    }
}

// ---------------------------------------------------------------------------
// Fused tensor-core GEMM: 11 passes (7 rel -> g_h fp16, 4 root -> out fp32)
// per 256-node tile. fp16 2-product split: D += Xh*Wh + Xh*Wl
// (x rounded to fp16; W split hi/lo). 2 CTAs/SM cover staging stalls.
// ---------------------------------------------------------------------------
__global__ void __launch_bounds__(256, 2) fused_mma_kernel(
        const float* __restrict__ x,
        const int*   __restrict__ node_type,
        const float* __restrict__ b_root,
        float* __restrict__ out) {
    extern __shared__ char smem_raw[];
    const uint32_t sb = smem_u32(smem_raw);
    __half* sX = (__half*)(smem_raw + OFF_X);

    const int tid  = threadIdx.x;
    const int warp = tid >> 5;
    const int lane = tid & 31;
    const int n0   = blockIdx.x * TILE_M;

    // ---- stage x (fp16): one row (128 floats) per thread ----
    {
        const int row  = tid;
        const bool vld = (n0 + row) < N_NODES;
        const float2* xr = (const float2*)(x + (size_t)(n0 + row) * IC);
        __half2* ph = (__half2*)(sX + row * XPITCH);
#pragma unroll
        for (int j = 0; j < 64; j++) {
            float2 v = vld ? xr[j] : make_float2(0.f, 0.f);
            ph[j] = __floats2half2_rn(v.x, v.y);
        }
    }

    // epilogue row/col mapping (per 16-row sub-tile s: rows rs0, rs0+8)
    const int cb = (lane & 3) * 2;
    int  rr[2][2];  bool vv[2][2];  int tt[2][2];
#pragma unroll
    for (int s = 0; s < 2; s++) {
        rr[s][0] = n0 + warp * 32 + s * 16 + (lane >> 2);
        rr[s][1] = rr[s][0] + 8;
#pragma unroll
        for (int u = 0; u < 2; u++) {
            vv[s][u] = rr[s][u] < N_NODES;
            tt[s][u] = vv[s][u] ? node_type[rr[s][u]] : -1;
        }
    }

    // ldmatrix base addresses (byte, shared space)
    const int lrow  = (lane & 7) + ((lane >> 3) & 1) * 8;
    const int lcol8 = (lane >> 4) * 8;
    uint32_t aBase[2];
#pragma unroll
    for (int s = 0; s < 2; s++)
        aBase[s] = sb + OFF_X +
            (uint32_t)((warp * 32 + s * 16 + lrow) * XPITCH + lcol8) * 2;
    const uint32_t bBaseH = sb + OFF_W + (uint32_t)(lrow * WPITCH + lcol8) * 2;
    const uint32_t bBaseL = bBaseH + WHALF;

    for (int pass = 0; pass < NPASS; pass++) {
        __syncthreads();   // prior pass done reading sW (pass 0: covers x stage)
        stage_w_async(sb, pass, tid);
        cp_commit();
        cp_wait0();
        __syncthreads();

        float acc[2][8][4];
#pragma unroll
        for (int s = 0; s < 2; s++)
#pragma unroll
            for (int nt = 0; nt < 8; nt++)
#pragma unroll
                for (int q = 0; q < 4; q++) acc[s][nt][q] = 0.f;

#pragma unroll 2
        for (int kc = 0; kc < 8; kc++) {
            uint32_t ah[2][4], bh[4][4], bl[4][4];
#pragma unroll
            for (int s = 0; s < 2; s++)
                ldsm_x4(ah[s], aBase[s] + kc * 32);
#pragma unroll
            for (int p = 0; p < 4; p++) {
                uint32_t bo = (uint32_t)(kc * 16 * WPITCH + p * 16) * 2;
                ldsm_x4_t(bh[p], bBaseH + bo);
                ldsm_x4_t(bl[p], bBaseL + bo);
            }
            // product groups issued far apart to break accumulator RAW chains
#pragma unroll
            for (int p = 0; p < 4; p++)
#pragma unroll
                for (int s = 0; s < 2; s++) {
                    mma_f16(acc[s][p * 2],     ah[s], bh[p]);
                    mma_f16(acc[s][p * 2 + 1], ah[s], bh[p] + 2);
                }
#pragma unroll
            for (int p = 0; p < 4; p++)
#pragma unroll
                for (int s = 0; s < 2; s++) {
                    mma_f16(acc[s][p * 2],     ah[s], bl[p]);
                    mma_f16(acc[s][p * 2 + 1], ah[s], bl[p] + 2);
                }
        }

        if (pass < NREL) {
            __half* hb = g_h + (size_t)pass * N_NODES * OC;
#pragma unroll
            for (int s = 0; s < 2; s++)
#pragma unroll
                for (int nt = 0; nt < 8; nt++) {
                    int c = nt * 8 + cb;
                    if (vv[s][0]) {
                        __half2 hv = __floats2half2_rn(acc[s][nt][0],
                                                       acc[s][nt][1]);
                        stg_cs_u32(hb + (size_t)rr[s][0] * OC + c,
                                   *(uint32_t*)&hv);
                    }
                    if (vv[s][1]) {
                        __half2 hv = __floats2half2_rn(acc[s][nt][2],
                                                       acc[s][nt][3]);
                        stg_cs_u32(hb + (size_t)rr[s][1] * OC + c,
                                   *(uint32_t*)&hv);
                    }
                }
        } else {
            int t = pass - NREL;
            const float* bp = b_root + t * OC;
#pragma unroll
            for (int s = 0; s < 2; s++)
#pragma unroll
                for (int nt = 0; nt < 8; nt++) {
                    int c = nt * 8 + cb;
                    if (tt[s][0] == t)
                        *(float2*)(out + (size_t)rr[s][0] * OC + c) =
                            make_float2(acc[s][nt][0] + bp[c],
                                        acc[s][nt][1] + bp[c + 1]);
                    if (tt[s][1] == t)
                        *(float2*)(out + (size_t)rr[s][1] * OC + c) =
                            make_float2(acc[s][nt][2] + bp[c],
                                        acc[s][nt][3] + bp[c + 1]);
                }
        }
    }
}

// ---------------------------------------------------------------------------
// Gather: one warp per dst node. out[dst] += sum_e w_e * h[rel_e][src_e].
// Lane owns 2 output floats (half2 per lane). No atomics; 4-wide batched
// loads for MLP over the random h-row gather.
// ---------------------------------------------------------------------------
__global__ void __launch_bounds__(256) gather_kernel(float* __restrict__ out) {
    const int dst  = (blockIdx.x * 256 + threadIdx.x) >> 5;   // 8 warps/block
    const int lane = threadIdx.x & 31;

    int deg = g_deg[dst];
    if (deg > CAP) deg = CAP;
    if (deg == 0) return;

    const uint32_t* bk = g_bkt + (size_t)dst * CAP;
    const float*    iv = g_inv + dst * NREL;

    float2 acc = make_float2(0.f, 0.f);
    int i = 0;
    for (; i + 4 <= deg; i += 4) {
        uint32_t e0 = bk[i], e1 = bk[i + 1], e2 = bk[i + 2], e3 = bk[i + 3];
        const __half2* p0 = (const __half2*)(g_h +
            ((size_t)(e0 >> 19) * N_NODES + (e0 & 0x7FFFF)) * OC) + lane;
        const __half2* p1 = (const __half2*)(g_h +
            ((size_t)(e1 >> 19) * N_NODES + (e1 & 0x7FFFF)) * OC) + lane;
        const __half2* p2 = (const __half2*)(g_h +
            ((size_t)(e2 >> 19) * N_NODES + (e2 & 0x7FFFF)) * OC) + lane;
        const __half2* p3 = (const __half2*)(g_h +
            ((size_t)(e3 >> 19) * N_NODES + (e3 & 0x7FFFF)) * OC) + lane;
        __half2 h0 = __ldcs(p0), h1 = __ldcs(p1), h2 = __ldcs(p2), h3 = __ldcs(p3);
        float w0 = iv[e0 >> 19], w1 = iv[e1 >> 19];
        float w2 = iv[e2 >> 19], w3 = iv[e3 >> 19];
        float2 f0 = __half22float2(h0), f1 = __half22float2(h1);
        float2 f2 = __half22float2(h2), f3 = __half22float2(h3);
        acc.x += w0 * f0.x + w1 * f1.x + w2 * f2.x + w3 * f3.x;
        acc.y += w0 * f0.y + w1 * f1.y + w2 * f2.y + w3 * f3.y;
    }
    for (; i < deg; i++) {
        uint32_t e = bk[i];
        const __half2* p = (const __half2*)(g_h +
            ((size_t)(e >> 19) * N_NODES + (e & 0x7FFFF)) * OC) + lane;
        float2 f = __half22float2(__ldcs(p));
        float w = iv[e >> 19];
        acc.x += w * f.x;
        acc.y += w * f.y;
    }

    float2* op = (float2*)(out + (size_t)dst * OC) + lane;
    float2 cur = *op;
    *op = make_float2(cur.x + acc.x, cur.y + acc.y);
}

// ---------------------------------------------------------------------------
// Launch
// ---------------------------------------------------------------------------
extern "C" void kernel_launch(void* const* d_in, const int* in_sizes, int n_in,
                              void* d_out, int out_size) {
    const float* x          = (const float*)d_in[0];
    const int*   edge_index = (const int*)d_in[1];
    const int*   edge_type  = (const int*)d_in[2];
    const int*   node_type  = (const int*)d_in[3];
    const float* W_rel      = (const float*)d_in[4];
    const float* W_root     = (const float*)d_in[5];
    const float* b_root     = (const float*)d_in[6];
    float*       out        = (float*)d_out;

    const int nr = N_NODES * NREL;
    zero_kernel<<<(nr + 255) / 256, 256>>>();
    count_fill_kernel<<<(N_EDGES + 255) / 256, 256>>>(edge_index, edge_type);
    inv_kernel<<<(nr + 255) / 256, 256>>>();
    conv_w_kernel<<<(NPASS * IC * OC + 255) / 256, 256>>>(W_rel, W_root);

    (void)cudaFuncSetAttribute(fused_mma_kernel,
                               cudaFuncAttributeMaxDynamicSharedMemorySize,
                               SMEM_DYN);
    fused_mma_kernel<<<NBLK, 256, SMEM_DYN>>>(x, node_type, b_root, out);

    gather_kernel<<<N_NODES / 8, 256>>>(out);
}